// round 6
// baseline (speedup 1.0000x reference)
#include <cuda_runtime.h>
#include <math.h>
#include <stdint.h>

#define DIM     768
#define NHEADS  12
#define HD      64
#define BATCH   8
#define SEQ     1024
#define MROWS   (BATCH*SEQ)     /* 8192 */
#define QKVN    (3*DIM)         /* 2304 */
#define SC2     0.1803368801111244f   /* 64^-0.5 * log2(e) */
#define GK      768
#define NCHUNK  24

// Scratch (allocation-free rule: __device__ globals)
__device__ __align__(1024) float g_qkv[(size_t)MROWS * QKVN];   // [B*N, 3*DIM]
__device__ __align__(1024) float g_att[(size_t)MROWS * DIM];    // [B*N, DIM]

__device__ __forceinline__ uint32_t smem_u32(const void* p) {
    uint32_t a;
    asm("{ .reg .u64 t; cvta.to.shared.u64 t, %1; cvt.u32.u64 %0, t; }"
        : "=r"(a) : "l"(p));
    return a;
}
__device__ __forceinline__ uint32_t f2tf32(float f) {
    uint32_t u;
    asm("cvt.rna.tf32.f32 %0, %1;" : "=r"(u) : "f"(f));
    return u;
}
__device__ __forceinline__ float ex2(float x) {
    float r;
    asm("ex2.approx.ftz.f32 %0, %1;" : "=f"(r) : "f"(x));
    return r;
}
__device__ __forceinline__ void mma_tf32(float* c, const uint32_t* a,
                                         const uint32_t* b) {
    asm volatile(
        "mma.sync.aligned.m16n8k8.row.col.f32.tf32.tf32.f32 "
        "{%0,%1,%2,%3}, {%4,%5,%6,%7}, {%8,%9}, {%0,%1,%2,%3};"
        : "+f"(c[0]), "+f"(c[1]), "+f"(c[2]), "+f"(c[3])
        : "r"(a[0]), "r"(a[1]), "r"(a[2]), "r"(a[3]), "r"(b[0]), "r"(b[1]));
}

// ===========================================================================
// tf32 mma.sync GEMM (validated round 4/5): C[M,N] = A[M,768] @ W[768,N] + bias
// ===========================================================================
__global__ __launch_bounds__(256, 1)
void gemm_mma(const float* __restrict__ A, const float* __restrict__ W,
              const float* __restrict__ bias, float* __restrict__ C, int N)
{
    extern __shared__ float sm[];
    const uint32_t sbase = smem_u32(sm);
    const int tid  = threadIdx.x;
    const int lane = tid & 31, wid = tid >> 5;
    const int wm   = wid >> 2, wn = wid & 3;
    const int bm   = blockIdx.y * 128, bn = blockIdx.x * 128;

    float acc[4][4][4];
    #pragma unroll
    for (int mi = 0; mi < 4; mi++)
        #pragma unroll
        for (int ni = 0; ni < 4; ni++)
            #pragma unroll
            for (int r = 0; r < 4; r++) acc[mi][ni][r] = 0.f;

    int a_row[4], a_c0[4], b_k[4], b_n0[4];
    #pragma unroll
    for (int i = 0; i < 4; i++) {
        int idx = i * 256 + tid;
        a_row[i] = idx >> 3;
        a_c0[i]  = (idx & 7) * 4;
        b_k[i]   = idx >> 5;
        b_n0[i]  = (idx & 31) * 4;
    }

    float4 ga[4], gb[4];

    #define LOADG(c)                                                          \
        do {                                                                  \
            _Pragma("unroll")                                                 \
            for (int i = 0; i < 4; i++)                                       \
                ga[i] = *(const float4*)&A[(size_t)(bm + a_row[i]) * GK       \
                                           + (c) * 32 + a_c0[i]];             \
            _Pragma("unroll")                                                 \
            for (int i = 0; i < 4; i++)                                       \
                gb[i] = *(const float4*)&W[(size_t)((c) * 32 + b_k[i]) * N    \
                                           + bn + b_n0[i]];                   \
        } while (0)

    #define STORES(s)                                                         \
        do {                                                                  \
            const uint32_t sA = sbase + (uint32_t)(s) * 32768u;               \
            const uint32_t sB = sA + 16384u;                                  \
            _Pragma("unroll")                                                 \
            for (int i = 0; i < 4; i++) {                                     \
                int row = a_row[i], c0 = a_c0[i];                             \
                int kt = c0 >> 3, c8hi = (c0 & 4) >> 2;                       \
                int mt = row >> 4, r8 = row & 15;                             \
                uint32_t tb = (uint32_t)((kt * 8 + mt) << 9);                 \
                uint32_t sw = (uint32_t)((kt << 5) ^ ((r8 & 2) << 3));        \
                uint32_t reg = (uint32_t)((r8 >> 3) + 2 * c8hi);              \
                float v[4] = {ga[i].x, ga[i].y, ga[i].z, ga[i].w};            \
                _Pragma("unroll")                                             \
                for (int j = 0; j < 4; j++) {                                 \
                    uint32_t ln = (uint32_t)(((r8 & 7) * 4 + j));             \
                    uint32_t off = (tb + (ln << 4) + (reg << 2)) ^ sw;        \
                    asm volatile("st.shared.b32 [%0], %1;"                    \
                                 :: "r"(sA + off), "r"(f2tf32(v[j]))          \
                                 : "memory");                                 \
                }                                                             \
            }                                                                 \
            _Pragma("unroll")                                                 \
            for (int i = 0; i < 4; i++) {                                     \
                int k = b_k[i], n0 = b_n0[i];                                 \
                int kt = k >> 3, k8 = k & 7;                                  \
                uint32_t reg = (uint32_t)(k8 >> 2);                           \
                uint32_t k3  = (uint32_t)(k8 & 3);                            \
                float v[4] = {gb[i].x, gb[i].y, gb[i].z, gb[i].w};            \
                _Pragma("unroll")                                             \
                for (int j = 0; j < 4; j++) {                                 \
                    int n = n0 + j, nt = n >> 3, n8 = n & 7;                  \
                    uint32_t off = (uint32_t)(((kt * 16 + nt) << 8)           \
                                 + ((n8 * 4 + (int)k3) << 3) + (reg << 2));   \
                    off ^= (uint32_t)(nt << 3);                               \
                    asm volatile("st.shared.b32 [%0], %1;"                    \
                                 :: "r"(sB + off), "r"(f2tf32(v[j]))          \
                                 : "memory");                                 \
                }                                                             \
            }                                                                 \
        } while (0)

    LOADG(0);
    STORES(0);
    __syncthreads();

    for (int c = 0; c < NCHUNK; c++) {
        if (c + 1 < NCHUNK) LOADG(c + 1);

        const uint32_t sA = sbase + (uint32_t)(c & 1) * 32768u;
        const uint32_t sB = sA + 16384u;
        #pragma unroll
        for (int ks = 0; ks < 4; ks++) {
            uint32_t af[4][4], bf[4][2];
            #pragma unroll
            for (int mi = 0; mi < 4; mi++) {
                uint32_t off = (uint32_t)(((ks * 8 + wm * 4 + mi) << 9)
                             + (lane << 4));
                off ^= (uint32_t)((ks << 5) ^ ((lane & 8) << 1));
                asm volatile("ld.shared.v4.b32 {%0,%1,%2,%3}, [%4];"
                             : "=r"(af[mi][0]), "=r"(af[mi][1]),
                               "=r"(af[mi][2]), "=r"(af[mi][3])
                             : "r"(sA + off));
            }
            #pragma unroll
            for (int ni = 0; ni < 4; ni++) {
                int bnt = wn * 4 + ni;
                uint32_t off = (uint32_t)(((ks * 16 + bnt) << 8) + (lane << 3));
                off ^= (uint32_t)(bnt << 3);
                asm volatile("ld.shared.v2.b32 {%0,%1}, [%2];"
                             : "=r"(bf[ni][0]), "=r"(bf[ni][1])
                             : "r"(sB + off));
            }
            #pragma unroll
            for (int mi = 0; mi < 4; mi++)
                #pragma unroll
                for (int ni = 0; ni < 4; ni++)
                    mma_tf32(acc[mi][ni], af[mi], bf[ni]);
        }

        if (c + 1 < NCHUNK) STORES((c + 1) & 1);
        __syncthreads();
    }

    #pragma unroll
    for (int mi = 0; mi < 4; mi++) {
        int row = bm + wm * 64 + mi * 16 + (lane >> 2);
        #pragma unroll
        for (int ni = 0; ni < 4; ni++) {
            int col = bn + wn * 32 + ni * 8 + (lane & 3) * 2;
            float2 bb = *(const float2*)&bias[col];
            float2 o0, o1;
            o0.x = acc[mi][ni][0] + bb.x;
            o0.y = acc[mi][ni][1] + bb.y;
            o1.x = acc[mi][ni][2] + bb.x;
            o1.y = acc[mi][ni][3] + bb.y;
            *(float2*)&C[(size_t)row * N + col]       = o0;
            *(float2*)&C[(size_t)(row + 8) * N + col] = o1;
        }
    }
    #undef LOADG
    #undef STORES
}

// ===========================================================================
// Tensor-core flash attention v2. CTA = (b, h, 64-q tile), 128 threads.
// P transformed S-accum -> A-fragment IN REGISTERS (shuffle butterfly), no
// P smem. SMEM = Ks | Vs (32 KB). __launch_bounds__(128,3) -> 3 CTAs/SM.
// ===========================================================================
__global__ __launch_bounds__(128, 3)
void attn_mma()
{
    extern __shared__ uint32_t smu[];
    const uint32_t sb  = smem_u32(smu);
    const uint32_t KsB = sb, VsB = sb + 16384u;

    const int tid  = threadIdx.x;
    const int lane = tid & 31, w = tid >> 5;
    const int b    = blockIdx.y / NHEADS;
    const int h    = blockIdx.y % NHEADS;
    const int q0   = blockIdx.x * 64;

    const float* base = g_qkv + (size_t)b * SEQ * QKVN + h * HD;

    // ---- Q into registers as A-fragments (pre-scaled to exp2 domain) ----
    const int r0w = w * 16 + (lane >> 2);     // CTA-local q row (0..63)
    const int c0  = lane & 3;
    uint32_t qa[8][4];
    {
        const float* Qp0 = base + (size_t)(q0 + r0w) * QKVN;
        const float* Qp1 = Qp0 + 8 * QKVN;
        #pragma unroll
        for (int ks = 0; ks < 8; ks++) {
            qa[ks][0] = f2tf32(Qp0[ks * 8 + c0]     * SC2);
            qa[ks][1] = f2tf32(Qp1[ks * 8 + c0]     * SC2);
            qa[ks][2] = f2tf32(Qp0[ks * 8 + c0 + 4] * SC2);
            qa[ks][3] = f2tf32(Qp1[ks * 8 + c0 + 4] * SC2);
        }
    }

    float oacc[8][4];
    #pragma unroll
    for (int nt = 0; nt < 8; nt++)
        #pragma unroll
        for (int r = 0; r < 4; r++) oacc[nt][r] = 0.f;
    float m0 = -INFINITY, m1 = -INFINITY, l0 = 0.f, l1 = 0.f;

    // shuffle-transform lane constants (S-accum cols 2c,2c+1 -> A cols c,c+4)
    const int srcA = (lane & ~3) | ((lane & 3) >> 1);
    const int srcB = srcA + 2;
    const bool odd = (lane & 1) != 0;

    // K/V fill coordinates
    const int krr = tid >> 4, kd0 = (tid & 15) * 4;      // K: 8 rows/pass
    const int vrr = tid & 31, vd0 = (tid >> 5) * 4;      // V: 32 rows/pass

    for (int kt = 0; kt < SEQ / 64; kt++) {
        __syncthreads();   // prev iter's PV (reads Vs) must finish

        // ---- fill K tile (b-frag native for QK^T: n=kv, k=hd) ----
        {
            const float* Kg = base + DIM + (size_t)(kt * 64) * QKVN;
            float4 t[8];
            #pragma unroll
            for (int p = 0; p < 8; p++)
                t[p] = *(const float4*)(Kg + (size_t)(p * 8 + krr) * QKVN + kd0);
            #pragma unroll
            for (int p = 0; p < 8; p++) {
                int r = p * 8 + krr;
                float v[4] = {t[p].x, t[p].y, t[p].z, t[p].w};
                #pragma unroll
                for (int e = 0; e < 4; e++) {
                    int d = kd0 + e;
                    uint32_t ln   = (uint32_t)(((r & 7) << 2) | (d & 3));
                    uint32_t word = (uint32_t)(((r >> 3) * 8 + (d >> 3)) << 6)
                                  + ((ln * 2u + (uint32_t)((d >> 2) & 1))
                                     ^ (uint32_t)((d >> 3) << 2));
                    asm volatile("st.shared.b32 [%0], %1;"
                                 :: "r"(KsB + word * 4u), "r"(f2tf32(v[e]))
                                 : "memory");
                }
            }
        }
        // ---- fill V^T tile (b-frag native for PV: n=hd, k=kv) ----
        {
            const float* Vg = base + 2 * DIM + (size_t)(kt * 64) * QKVN;
            float4 t[8];
            #pragma unroll
            for (int p = 0; p < 8; p++) {
                int r  = (p & 1) * 32 + vrr;
                int d0 = (p >> 1) * 16 + vd0;
                t[p] = *(const float4*)(Vg + (size_t)r * QKVN + d0);
            }
            #pragma unroll
            for (int p = 0; p < 8; p++) {
                int r  = (p & 1) * 32 + vrr;
                int d0 = (p >> 1) * 16 + vd0;
                float v[4] = {t[p].x, t[p].y, t[p].z, t[p].w};
                #pragma unroll
                for (int e = 0; e < 4; e++) {
                    int d = d0 + e;
                    uint32_t ln   = (uint32_t)(((d & 7) << 2) | (r & 3));
                    uint32_t word = (uint32_t)(((d >> 3) * 8 + (r >> 3)) << 6)
                                  + ((ln * 2u + (uint32_t)((r >> 2) & 1))
                                     ^ (uint32_t)((r >> 3) << 2));
                    asm volatile("st.shared.b32 [%0], %1;"
                                 :: "r"(VsB + word * 4u), "r"(f2tf32(v[e]))
                                 : "memory");
                }
            }
        }
        __syncthreads();

        // ---- S = Q K^T ----
        float sacc[8][4];
        #pragma unroll
        for (int nt = 0; nt < 8; nt++)
            #pragma unroll
            for (int r = 0; r < 4; r++) sacc[nt][r] = 0.f;

        #pragma unroll
        for (int ks = 0; ks < 8; ks++) {
            uint32_t bf[8][2];
            #pragma unroll
            for (int nt = 0; nt < 8; nt++) {
                uint32_t off = (uint32_t)((nt * 8 + ks) << 6)
                             + (((uint32_t)lane * 2u) ^ (uint32_t)(ks << 2));
                asm volatile("ld.shared.v2.b32 {%0,%1}, [%2];"
                             : "=r"(bf[nt][0]), "=r"(bf[nt][1])
                             : "r"(KsB + off * 4u));
            }
            #pragma unroll
            for (int nt = 0; nt < 8; nt++)
                mma_tf32(sacc[nt], qa[ks], bf[nt]);
        }

        // ---- online softmax (exp2 domain) ----
        float mx0 = -INFINITY, mx1 = -INFINITY;
        #pragma unroll
        for (int nt = 0; nt < 8; nt++) {
            mx0 = fmaxf(mx0, fmaxf(sacc[nt][0], sacc[nt][1]));
            mx1 = fmaxf(mx1, fmaxf(sacc[nt][2], sacc[nt][3]));
        }
        mx0 = fmaxf(mx0, __shfl_xor_sync(0xffffffffu, mx0, 1));
        mx0 = fmaxf(mx0, __shfl_xor_sync(0xffffffffu, mx0, 2));
        mx1 = fmaxf(mx1, __shfl_xor_sync(0xffffffffu, mx1, 1));
        mx1 = fmaxf(mx1, __shfl_xor_sync(0xffffffffu, mx1, 2));
        float mn0 = fmaxf(m0, mx0), mn1 = fmaxf(m1, mx1);
        float a0 = ex2(m0 - mn0), a1 = ex2(m1 - mn1);
        m0 = mn0; m1 = mn1;
        l0 *= a0;  l1 *= a1;
        #pragma unroll
        for (int nt = 0; nt < 8; nt++) {
            oacc[nt][0] *= a0; oacc[nt][1] *= a0;
            oacc[nt][2] *= a1; oacc[nt][3] *= a1;
        }

        // ---- exp + shuffle-transform P + PV, fused per kv-chunk ----
        float sum0 = 0.f, sum1 = 0.f;
        #pragma unroll
        for (int nt = 0; nt < 8; nt++) {   // nt = kv chunk (k=8 of PV)
            float p00 = ex2(sacc[nt][0] - m0);
            float p01 = ex2(sacc[nt][1] - m0);
            float p10 = ex2(sacc[nt][2] - m1);
            float p11 = ex2(sacc[nt][3] - m1);
            sum0 += p00 + p01;
            sum1 += p10 + p11;

            float u00 = __shfl_sync(0xffffffffu, p00, srcA);
            float u01 = __shfl_sync(0xffffffffu, p01, srcA);
            float u10 = __shfl_sync(0xffffffffu, p10, srcA);
            float u11 = __shfl_sync(0xffffffffu, p11, srcA);
            float u20 = __shfl_sync(0xffffffffu, p00, srcB);
            float u21 = __shfl_sync(0xffffffffu, p01, srcB);
            float u30 = __shfl_sync(0xffffffffu, p10, srcB);
            float u31 = __shfl_sync(0xffffffffu, p11, srcB);

            uint32_t pa[4];
            pa[0] = f2tf32(odd ? u01 : u00);
            pa[1] = f2tf32(odd ? u11 : u10);
            pa[2] = f2tf32(odd ? u21 : u20);
            pa[3] = f2tf32(odd ? u31 : u30);

            #pragma unroll
            for (int ht = 0; ht < 8; ht++) {   // ht = hd 8-col tile
                uint32_t vb[2];
                uint32_t off = (uint32_t)((ht * 8 + nt) << 6)
                             + (((uint32_t)lane * 2u) ^ (uint32_t)(nt << 2));
                asm volatile("ld.shared.v2.b32 {%0,%1}, [%2];"
                             : "=r"(vb[0]), "=r"(vb[1]) : "r"(VsB + off * 4u));
                mma_tf32(oacc[ht], pa, vb);
            }
        }
        sum0 += __shfl_xor_sync(0xffffffffu, sum0, 1);
        sum0 += __shfl_xor_sync(0xffffffffu, sum0, 2);
        sum1 += __shfl_xor_sync(0xffffffffu, sum1, 1);
        sum1 += __shfl_xor_sync(0xffffffffu, sum1, 2);
        l0 += sum0; l1 += sum1;
    }

    // ---- normalize, write out [B*N, DIM] (col = h*64 + d) ----
    {
        float inv0 = 1.f / l0, inv1 = 1.f / l1;
        float* O0 = g_att + (size_t)(b * SEQ + q0 + r0w) * DIM + h * HD;
        float* O1 = O0 + 8 * DIM;
        const int cc0 = 2 * c0;
        #pragma unroll
        for (int nt = 0; nt < 8; nt++) {
            int col = nt * 8 + cc0;
            float2 v0 = {oacc[nt][0] * inv0, oacc[nt][1] * inv0};
            float2 v1 = {oacc[nt][2] * inv1, oacc[nt][3] * inv1};
            *(float2*)(O0 + col) = v0;
            *(float2*)(O1 + col) = v1;
        }
    }
}

// ---------------------------------------------------------------------------
extern "C" void kernel_launch(void* const* d_in, const int* in_sizes, int n_in,
                              void* d_out, int out_size)
{
    const float* x      = (const float*)d_in[0];
    const float* w_qkv  = (const float*)d_in[1];
    const float* b_qkv  = (const float*)d_in[2];
    const float* w_proj = (const float*)d_in[3];
    const float* b_proj = (const float*)d_in[4];
    float* out = (float*)d_out;

    float* qkv = nullptr;
    float* att = nullptr;
    cudaGetSymbolAddress((void**)&qkv, g_qkv);
    cudaGetSymbolAddress((void**)&att, g_att);

    const int gemm_smem = 65536;
    const int attn_smem = 32768;
    cudaFuncSetAttribute(gemm_mma,
                         cudaFuncAttributeMaxDynamicSharedMemorySize, gemm_smem);
    cudaFuncSetAttribute(attn_mma,
                         cudaFuncAttributeMaxDynamicSharedMemorySize, attn_smem);

    // 1) QKV projection: [8192,768] @ [768,2304] + bias   (tf32 mma.sync)
    gemm_mma<<<dim3(QKVN / 128, MROWS / 128), 256, gemm_smem>>>(
        x, w_qkv, b_qkv, qkv, QKVN);

    // 2) Tensor-core flash attention (register-P version)
    attn_mma<<<dim3(SEQ / 64, BATCH * NHEADS), 128, attn_smem>>>();

    // 3) Output projection: [8192,768] @ [768,768] + bias (tf32 mma.sync)
    gemm_mma<<<dim3(DIM / 128, MROWS / 128), 256, gemm_smem>>>(
        att, w_proj, b_proj, out, DIM);
}

// round 7
// speedup vs baseline: 1.2188x; 1.2188x over previous
#include <cuda_runtime.h>
#include <math.h>
#include <stdint.h>

#define DIM     768
#define NHEADS  12
#define HD      64
#define BATCH   8
#define SEQ     1024
#define MROWS   (BATCH*SEQ)     /* 8192 */
#define QKVN    (3*DIM)         /* 2304 */
#define SC2     0.1803368801111244f   /* 64^-0.5 * log2(e) */
#define GK      768
#define NCHUNK  24

// Scratch (allocation-free rule: __device__ globals)
__device__ __align__(1024) float    g_qkv[(size_t)MROWS * QKVN];  // [B*N, 3*DIM]
__device__ __align__(1024) float    g_att[(size_t)MROWS * DIM];   // [B*N, DIM]
__device__ __align__(1024) uint32_t g_kvf[(size_t)BATCH * NHEADS * 16 * 8192];
// g_kvf[(bh*16+kt)*8192]: K tile (4096 words, b-frag native) | V^T tile (4096)

__device__ __forceinline__ uint32_t smem_u32(const void* p) {
    uint32_t a;
    asm("{ .reg .u64 t; cvta.to.shared.u64 t, %1; cvt.u32.u64 %0, t; }"
        : "=r"(a) : "l"(p));
    return a;
}
__device__ __forceinline__ uint32_t f2tf32(float f) {
    uint32_t u;
    asm("cvt.rna.tf32.f32 %0, %1;" : "=r"(u) : "f"(f));
    return u;
}
__device__ __forceinline__ float ex2(float x) {
    float r;
    asm("ex2.approx.ftz.f32 %0, %1;" : "=f"(r) : "f"(x));
    return r;
}
__device__ __forceinline__ void mma_tf32(float* c, const uint32_t* a,
                                         const uint32_t* b) {
    asm volatile(
        "mma.sync.aligned.m16n8k8.row.col.f32.tf32.tf32.f32 "
        "{%0,%1,%2,%3}, {%4,%5,%6,%7}, {%8,%9}, {%0,%1,%2,%3};"
        : "+f"(c[0]), "+f"(c[1]), "+f"(c[2]), "+f"(c[3])
        : "r"(a[0]), "r"(a[1]), "r"(a[2]), "r"(a[3]), "r"(b[0]), "r"(b[1]));
}

// ===========================================================================
// tf32 mma.sync GEMM (validated): C[M,N] = A[M,768] @ W[768,N] + bias
// ===========================================================================
__global__ __launch_bounds__(256, 1)
void gemm_mma(const float* __restrict__ A, const float* __restrict__ W,
              const float* __restrict__ bias, float* __restrict__ C, int N)
{
    extern __shared__ float sm[];
    const uint32_t sbase = smem_u32(sm);
    const int tid  = threadIdx.x;
    const int lane = tid & 31, wid = tid >> 5;
    const int wm   = wid >> 2, wn = wid & 3;
    const int bm   = blockIdx.y * 128, bn = blockIdx.x * 128;

    float acc[4][4][4];
    #pragma unroll
    for (int mi = 0; mi < 4; mi++)
        #pragma unroll
        for (int ni = 0; ni < 4; ni++)
            #pragma unroll
            for (int r = 0; r < 4; r++) acc[mi][ni][r] = 0.f;

    int a_row[4], a_c0[4], b_k[4], b_n0[4];
    #pragma unroll
    for (int i = 0; i < 4; i++) {
        int idx = i * 256 + tid;
        a_row[i] = idx >> 3;
        a_c0[i]  = (idx & 7) * 4;
        b_k[i]   = idx >> 5;
        b_n0[i]  = (idx & 31) * 4;
    }

    float4 ga[4], gb[4];

    #define LOADG(c)                                                          \
        do {                                                                  \
            _Pragma("unroll")                                                 \
            for (int i = 0; i < 4; i++)                                       \
                ga[i] = *(const float4*)&A[(size_t)(bm + a_row[i]) * GK       \
                                           + (c) * 32 + a_c0[i]];             \
            _Pragma("unroll")                                                 \
            for (int i = 0; i < 4; i++)                                       \
                gb[i] = *(const float4*)&W[(size_t)((c) * 32 + b_k[i]) * N    \
                                           + bn + b_n0[i]];                   \
        } while (0)

    #define STORES(s)                                                         \
        do {                                                                  \
            const uint32_t sA = sbase + (uint32_t)(s) * 32768u;               \
            const uint32_t sB = sA + 16384u;                                  \
            _Pragma("unroll")                                                 \
            for (int i = 0; i < 4; i++) {                                     \
                int row = a_row[i], c0 = a_c0[i];                             \
                int kt = c0 >> 3, c8hi = (c0 & 4) >> 2;                       \
                int mt = row >> 4, r8 = row & 15;                             \
                uint32_t tb = (uint32_t)((kt * 8 + mt) << 9);                 \
                uint32_t sw = (uint32_t)((kt << 5) ^ ((r8 & 2) << 3));        \
                uint32_t reg = (uint32_t)((r8 >> 3) + 2 * c8hi);              \
                float v[4] = {ga[i].x, ga[i].y, ga[i].z, ga[i].w};            \
                _Pragma("unroll")                                             \
                for (int j = 0; j < 4; j++) {                                 \
                    uint32_t ln = (uint32_t)(((r8 & 7) * 4 + j));             \
                    uint32_t off = (tb + (ln << 4) + (reg << 2)) ^ sw;        \
                    asm volatile("st.shared.b32 [%0], %1;"                    \
                                 :: "r"(sA + off), "r"(f2tf32(v[j]))          \
                                 : "memory");                                 \
                }                                                             \
            }                                                                 \
            _Pragma("unroll")                                                 \
            for (int i = 0; i < 4; i++) {                                     \
                int k = b_k[i], n0 = b_n0[i];                                 \
                int kt = k >> 3, k8 = k & 7;                                  \
                uint32_t reg = (uint32_t)(k8 >> 2);                           \
                uint32_t k3  = (uint32_t)(k8 & 3);                            \
                float v[4] = {gb[i].x, gb[i].y, gb[i].z, gb[i].w};            \
                _Pragma("unroll")                                             \
                for (int j = 0; j < 4; j++) {                                 \
                    int n = n0 + j, nt = n >> 3, n8 = n & 7;                  \
                    uint32_t off = (uint32_t)(((kt * 16 + nt) << 8)           \
                                 + ((n8 * 4 + (int)k3) << 3) + (reg << 2));   \
                    off ^= (uint32_t)(nt << 3);                               \
                    asm volatile("st.shared.b32 [%0], %1;"                    \
                                 :: "r"(sB + off), "r"(f2tf32(v[j]))          \
                                 : "memory");                                 \
                }                                                             \
            }                                                                 \
        } while (0)

    LOADG(0);
    STORES(0);
    __syncthreads();

    for (int c = 0; c < NCHUNK; c++) {
        if (c + 1 < NCHUNK) LOADG(c + 1);

        const uint32_t sA = sbase + (uint32_t)(c & 1) * 32768u;
        const uint32_t sB = sA + 16384u;
        #pragma unroll
        for (int ks = 0; ks < 4; ks++) {
            uint32_t af[4][4], bf[4][2];
            #pragma unroll
            for (int mi = 0; mi < 4; mi++) {
                uint32_t off = (uint32_t)(((ks * 8 + wm * 4 + mi) << 9)
                             + (lane << 4));
                off ^= (uint32_t)((ks << 5) ^ ((lane & 8) << 1));
                asm volatile("ld.shared.v4.b32 {%0,%1,%2,%3}, [%4];"
                             : "=r"(af[mi][0]), "=r"(af[mi][1]),
                               "=r"(af[mi][2]), "=r"(af[mi][3])
                             : "r"(sA + off));
            }
            #pragma unroll
            for (int ni = 0; ni < 4; ni++) {
                int bnt = wn * 4 + ni;
                uint32_t off = (uint32_t)(((ks * 16 + bnt) << 8) + (lane << 3));
                off ^= (uint32_t)(bnt << 3);
                asm volatile("ld.shared.v2.b32 {%0,%1}, [%2];"
                             : "=r"(bf[ni][0]), "=r"(bf[ni][1])
                             : "r"(sB + off));
            }
            #pragma unroll
            for (int mi = 0; mi < 4; mi++)
                #pragma unroll
                for (int ni = 0; ni < 4; ni++)
                    mma_tf32(acc[mi][ni], af[mi], bf[ni]);
        }

        if (c + 1 < NCHUNK) STORES((c + 1) & 1);
        __syncthreads();
    }

    #pragma unroll
    for (int mi = 0; mi < 4; mi++) {
        int row = bm + wm * 64 + mi * 16 + (lane >> 2);
        #pragma unroll
        for (int ni = 0; ni < 4; ni++) {
            int col = bn + wn * 32 + ni * 8 + (lane & 3) * 2;
            float2 bb = *(const float2*)&bias[col];
            float2 o0, o1;
            o0.x = acc[mi][ni][0] + bb.x;
            o0.y = acc[mi][ni][1] + bb.y;
            o1.x = acc[mi][ni][2] + bb.x;
            o1.y = acc[mi][ni][3] + bb.y;
            *(float2*)&C[(size_t)row * N + col]       = o0;
            *(float2*)&C[(size_t)(row + 8) * N + col] = o1;
        }
    }
    #undef LOADG
    #undef STORES
}

// ===========================================================================
// K/V -> fragment-native tf32 conversion, done ONCE per (b,h,kv-tile).
// Same word formulas as the validated round-5 in-kernel fill, STS -> STG.
// grid = (16 kv-tiles, B*H), 128 threads.
// ===========================================================================
__global__ __launch_bounds__(128)
void conv_kv()
{
    const int tid = threadIdx.x;
    const int bh  = blockIdx.y;
    const int kt  = blockIdx.x;
    const int b   = bh / NHEADS;
    const int h   = bh % NHEADS;

    const float* base = g_qkv + (size_t)b * SEQ * QKVN + h * HD;
    uint32_t* out = g_kvf + ((size_t)bh * 16 + kt) * 8192;

    // ---- K tile (b-frag native for QK^T: n=kv, k=hd) ----
    {
        const int krr = tid >> 4, kd0 = (tid & 15) * 4;
        const float* Kg = base + DIM + (size_t)(kt * 64) * QKVN;
        float4 t[8];
        #pragma unroll
        for (int p = 0; p < 8; p++)
            t[p] = *(const float4*)(Kg + (size_t)(p * 8 + krr) * QKVN + kd0);
        #pragma unroll
        for (int p = 0; p < 8; p++) {
            int r = p * 8 + krr;
            float v[4] = {t[p].x, t[p].y, t[p].z, t[p].w};
            #pragma unroll
            for (int e = 0; e < 4; e++) {
                int d = kd0 + e;
                uint32_t ln   = (uint32_t)(((r & 7) << 2) | (d & 3));
                uint32_t word = (uint32_t)(((r >> 3) * 8 + (d >> 3)) << 6)
                              + ((ln * 2u + (uint32_t)((d >> 2) & 1))
                                 ^ (uint32_t)((d >> 3) << 2));
                out[word] = f2tf32(v[e]);
            }
        }
    }
    // ---- V^T tile (b-frag native for PV: n=hd, k=kv) ----
    {
        const int vrr = tid & 31, vd0 = (tid >> 5) * 4;
        const float* Vg = base + 2 * DIM + (size_t)(kt * 64) * QKVN;
        float4 t[8];
        #pragma unroll
        for (int p = 0; p < 8; p++) {
            int r  = (p & 1) * 32 + vrr;
            int d0 = (p >> 1) * 16 + vd0;
            t[p] = *(const float4*)(Vg + (size_t)r * QKVN + d0);
        }
        #pragma unroll
        for (int p = 0; p < 8; p++) {
            int r  = (p & 1) * 32 + vrr;
            int d0 = (p >> 1) * 16 + vd0;
            float v[4] = {t[p].x, t[p].y, t[p].z, t[p].w};
            #pragma unroll
            for (int e = 0; e < 4; e++) {
                int d = d0 + e;
                uint32_t ln   = (uint32_t)(((d & 7) << 2) | (r & 3));
                uint32_t word = (uint32_t)(((d >> 3) * 8 + (r >> 3)) << 6)
                              + ((ln * 2u + (uint32_t)((r >> 2) & 1))
                                 ^ (uint32_t)((r >> 3) << 2));
                out[4096 + word] = f2tf32(v[e]);
            }
        }
    }
}

// ===========================================================================
// Tensor-core flash attention (round-5 mainloop, fill replaced by raw copy).
// CTA = (b, h, 64-q tile), 128 threads. SMEM: Ks | Vs | Ps (48 KB).
// ===========================================================================
__global__ __launch_bounds__(128)
void attn_mma()
{
    extern __shared__ uint32_t smu[];
    const uint32_t sb  = smem_u32(smu);
    const uint32_t KsB = sb, VsB = sb + 16384u, PsB = sb + 32768u;

    const int tid  = threadIdx.x;
    const int lane = tid & 31, w = tid >> 5;
    const int bh   = blockIdx.y;
    const int b    = bh / NHEADS;
    const int h    = bh % NHEADS;
    const int q0   = blockIdx.x * 64;

    const float* base = g_qkv + (size_t)b * SEQ * QKVN + h * HD;

    // ---- Q into registers as A-fragments (pre-scaled to exp2 domain) ----
    const int r0w = w * 16 + (lane >> 2);     // CTA-local q row (0..63)
    const int c0  = lane & 3;
    uint32_t qa[8][4];
    {
        const float* Qp0 = base + (size_t)(q0 + r0w) * QKVN;
        const float* Qp1 = Qp0 + 8 * QKVN;
        #pragma unroll
        for (int ks = 0; ks < 8; ks++) {
            qa[ks][0] = f2tf32(Qp0[ks * 8 + c0]     * SC2);
            qa[ks][1] = f2tf32(Qp1[ks * 8 + c0]     * SC2);
            qa[ks][2] = f2tf32(Qp0[ks * 8 + c0 + 4] * SC2);
            qa[ks][3] = f2tf32(Qp1[ks * 8 + c0 + 4] * SC2);
        }
    }

    float oacc[8][4];
    #pragma unroll
    for (int nt = 0; nt < 8; nt++)
        #pragma unroll
        for (int r = 0; r < 4; r++) oacc[nt][r] = 0.f;
    float m0 = -INFINITY, m1 = -INFINITY, l0 = 0.f, l1 = 0.f;

    // P-store positions (per lane constants)
    const int cc0 = 2 * c0, cc1 = cc0 + 1;
    const uint32_t pos0 = (uint32_t)((cc0 & 3) * 2 + (cc0 >> 2));
    const uint32_t pos1 = (uint32_t)((cc1 & 3) * 2 + (cc1 >> 2));
    const uint32_t swz  = (uint32_t)((r0w & 3) << 3);
    const uint32_t prow0 = PsB + (uint32_t)r0w * 256u;
    const uint32_t prow1 = prow0 + 8u * 256u;

    const uint4* kvsrc = (const uint4*)(g_kvf + (size_t)bh * 16 * 8192);

    for (int kt = 0; kt < SEQ / 64; kt++) {
        __syncthreads();   // prev iter's PV (reads Vs) must finish

        // ---- raw copy of pre-converted K|V tile: 32 KB, coalesced ----
        {
            const uint4* src = kvsrc + (size_t)kt * 2048;
            #pragma unroll
            for (int i = 0; i < 16; i++) {
                int idx = i * 128 + tid;
                uint4 t = src[idx];
                asm volatile("st.shared.v4.b32 [%0], {%1,%2,%3,%4};"
                             :: "r"(KsB + (uint32_t)idx * 16u),
                                "r"(t.x), "r"(t.y), "r"(t.z), "r"(t.w)
                             : "memory");
            }
        }
        __syncthreads();

        // ---- S = Q K^T ----
        float sacc[8][4];
        #pragma unroll
        for (int nt = 0; nt < 8; nt++)
            #pragma unroll
            for (int r = 0; r < 4; r++) sacc[nt][r] = 0.f;

        #pragma unroll
        for (int ks = 0; ks < 8; ks++) {
            uint32_t bf[8][2];
            #pragma unroll
            for (int nt = 0; nt < 8; nt++) {
                uint32_t off = (uint32_t)((nt * 8 + ks) << 6)
                             + (((uint32_t)lane * 2u) ^ (uint32_t)(ks << 2));
                asm volatile("ld.shared.v2.b32 {%0,%1}, [%2];"
                             : "=r"(bf[nt][0]), "=r"(bf[nt][1])
                             : "r"(KsB + off * 4u));
            }
            #pragma unroll
            for (int nt = 0; nt < 8; nt++)
                mma_tf32(sacc[nt], qa[ks], bf[nt]);
        }

        // ---- online softmax (exp2 domain) ----
        float mx0 = -INFINITY, mx1 = -INFINITY;
        #pragma unroll
        for (int nt = 0; nt < 8; nt++) {
            mx0 = fmaxf(mx0, fmaxf(sacc[nt][0], sacc[nt][1]));
            mx1 = fmaxf(mx1, fmaxf(sacc[nt][2], sacc[nt][3]));
        }
        mx0 = fmaxf(mx0, __shfl_xor_sync(0xffffffffu, mx0, 1));
        mx0 = fmaxf(mx0, __shfl_xor_sync(0xffffffffu, mx0, 2));
        mx1 = fmaxf(mx1, __shfl_xor_sync(0xffffffffu, mx1, 1));
        mx1 = fmaxf(mx1, __shfl_xor_sync(0xffffffffu, mx1, 2));
        float mn0 = fmaxf(m0, mx0), mn1 = fmaxf(m1, mx1);
        float a0 = ex2(m0 - mn0), a1 = ex2(m1 - mn1);
        m0 = mn0; m1 = mn1;
        l0 *= a0;  l1 *= a1;

        float sum0 = 0.f, sum1 = 0.f;
        #pragma unroll
        for (int nt = 0; nt < 8; nt++) {
            float p00 = ex2(sacc[nt][0] - m0);
            float p01 = ex2(sacc[nt][1] - m0);
            float p10 = ex2(sacc[nt][2] - m1);
            float p11 = ex2(sacc[nt][3] - m1);
            sum0 += p00 + p01;
            sum1 += p10 + p11;
            oacc[nt][0] *= a0; oacc[nt][1] *= a0;
            oacc[nt][2] *= a1; oacc[nt][3] *= a1;
            uint32_t nb = (uint32_t)(nt * 8);
            asm volatile("st.shared.b32 [%0], %1;"
                         :: "r"(prow0 + ((nb + pos0) ^ swz) * 4u),
                            "r"(f2tf32(p00)) : "memory");
            asm volatile("st.shared.b32 [%0], %1;"
                         :: "r"(prow0 + ((nb + pos1) ^ swz) * 4u),
                            "r"(f2tf32(p01)) : "memory");
            asm volatile("st.shared.b32 [%0], %1;"
                         :: "r"(prow1 + ((nb + pos0) ^ swz) * 4u),
                            "r"(f2tf32(p10)) : "memory");
            asm volatile("st.shared.b32 [%0], %1;"
                         :: "r"(prow1 + ((nb + pos1) ^ swz) * 4u),
                            "r"(f2tf32(p11)) : "memory");
        }
        sum0 += __shfl_xor_sync(0xffffffffu, sum0, 1);
        sum0 += __shfl_xor_sync(0xffffffffu, sum0, 2);
        sum1 += __shfl_xor_sync(0xffffffffu, sum1, 1);
        sum1 += __shfl_xor_sync(0xffffffffu, sum1, 2);
        l0 += sum0; l1 += sum1;

        // ---- O += P V  (P rows are warp-private: no barrier needed) ----
        #pragma unroll
        for (int ks = 0; ks < 8; ks++) {
            uint32_t pa[4];
            uint32_t wo = (((uint32_t)(ks * 8 + c0 * 2)) ^ swz) * 4u;
            asm volatile("ld.shared.v2.b32 {%0,%1}, [%2];"
                         : "=r"(pa[0]), "=r"(pa[2]) : "r"(prow0 + wo));
            asm volatile("ld.shared.v2.b32 {%0,%1}, [%2];"
                         : "=r"(pa[1]), "=r"(pa[3]) : "r"(prow1 + wo));
            #pragma unroll
            for (int nt = 0; nt < 8; nt++) {
                uint32_t vb[2];
                uint32_t off = (uint32_t)((nt * 8 + ks) << 6)
                             + (((uint32_t)lane * 2u) ^ (uint32_t)(ks << 2));
                asm volatile("ld.shared.v2.b32 {%0,%1}, [%2];"
                             : "=r"(vb[0]), "=r"(vb[1]) : "r"(VsB + off * 4u));
                mma_tf32(oacc[nt], pa, vb);
            }
        }
    }

    // ---- normalize, write out [B*N, DIM] (col = h*64 + d) ----
    {
        float inv0 = 1.f / l0, inv1 = 1.f / l1;
        float* O0 = g_att + (size_t)(b * SEQ + q0 + r0w) * DIM + h * HD;
        float* O1 = O0 + 8 * DIM;
        #pragma unroll
        for (int nt = 0; nt < 8; nt++) {
            int col = nt * 8 + cc0;
            float2 v0 = {oacc[nt][0] * inv0, oacc[nt][1] * inv0};
            float2 v1 = {oacc[nt][2] * inv1, oacc[nt][3] * inv1};
            *(float2*)(O0 + col) = v0;
            *(float2*)(O1 + col) = v1;
        }
    }
}

// ---------------------------------------------------------------------------
extern "C" void kernel_launch(void* const* d_in, const int* in_sizes, int n_in,
                              void* d_out, int out_size)
{
    const float* x      = (const float*)d_in[0];
    const float* w_qkv  = (const float*)d_in[1];
    const float* b_qkv  = (const float*)d_in[2];
    const float* w_proj = (const float*)d_in[3];
    const float* b_proj = (const float*)d_in[4];
    float* out = (float*)d_out;

    float* qkv = nullptr;
    float* att = nullptr;
    cudaGetSymbolAddress((void**)&qkv, g_qkv);
    cudaGetSymbolAddress((void**)&att, g_att);

    const int gemm_smem = 65536;
    const int attn_smem = 49152;
    cudaFuncSetAttribute(gemm_mma,
                         cudaFuncAttributeMaxDynamicSharedMemorySize, gemm_smem);
    cudaFuncSetAttribute(attn_mma,
                         cudaFuncAttributeMaxDynamicSharedMemorySize, attn_smem);

    // 1) QKV projection: [8192,768] @ [768,2304] + bias   (tf32 mma.sync)
    gemm_mma<<<dim3(QKVN / 128, MROWS / 128), 256, gemm_smem>>>(
        x, w_qkv, b_qkv, qkv, QKVN);

    // 2a) One-time K/V fragment-layout conversion
    conv_kv<<<dim3(16, BATCH * NHEADS), 128>>>();

    // 2b) Tensor-core flash attention (copy-fill)
    attn_mma<<<dim3(SEQ / 64, BATCH * NHEADS), 128, attn_smem>>>();

    // 3) Output projection: [8192,768] @ [768,768] + bias (tf32 mma.sync)
    gemm_mma<<<dim3(DIM / 128, MROWS / 128), 256, gemm_smem>>>(
        att, w_proj, b_proj, out, DIM);
}

// round 8
// speedup vs baseline: 1.3067x; 1.0721x over previous
#include <cuda_runtime.h>
#include <math.h>
#include <stdint.h>

#define DIM     768
#define NHEADS  12
#define HD      64
#define BATCH   8
#define SEQ     1024
#define MROWS   (BATCH*SEQ)     /* 8192 */
#define QKVN    (3*DIM)         /* 2304 */
#define SC2     0.1803368801111244f   /* 64^-0.5 * log2(e) */
#define GK      768
#define NCHUNK  24

// Scratch (allocation-free rule: __device__ globals)
__device__ __align__(1024) float    g_qkv[(size_t)MROWS * QKVN];  // [B*N, 3*DIM]
__device__ __align__(1024) float    g_att[(size_t)MROWS * DIM];   // [B*N, DIM]
__device__ __align__(1024) uint32_t g_kvf[(size_t)BATCH * NHEADS * 16 * 8192];
// g_kvf[(bh*16+kt)*8192]: K tile (4096 words, b-frag native) | V^T tile (4096)

__device__ __forceinline__ uint32_t smem_u32(const void* p) {
    uint32_t a;
    asm("{ .reg .u64 t; cvta.to.shared.u64 t, %1; cvt.u32.u64 %0, t; }"
        : "=r"(a) : "l"(p));
    return a;
}
__device__ __forceinline__ uint32_t f2tf32(float f) {
    uint32_t u;
    asm("cvt.rna.tf32.f32 %0, %1;" : "=r"(u) : "f"(f));
    return u;
}
__device__ __forceinline__ float ex2(float x) {
    float r;
    asm("ex2.approx.ftz.f32 %0, %1;" : "=f"(r) : "f"(x));
    return r;
}
__device__ __forceinline__ void mma_tf32(float* c, const uint32_t* a,
                                         const uint32_t* b) {
    asm volatile(
        "mma.sync.aligned.m16n8k8.row.col.f32.tf32.tf32.f32 "
        "{%0,%1,%2,%3}, {%4,%5,%6,%7}, {%8,%9}, {%0,%1,%2,%3};"
        : "+f"(c[0]), "+f"(c[1]), "+f"(c[2]), "+f"(c[3])
        : "r"(a[0]), "r"(a[1]), "r"(a[2]), "r"(a[3]), "r"(b[0]), "r"(b[1]));
}
__device__ __forceinline__ void cp_async16(uint32_t dst, const void* src) {
    asm volatile("cp.async.cg.shared.global [%0], [%1], 16;"
                 :: "r"(dst), "l"(src) : "memory");
}

// ===========================================================================
// tf32 mma.sync GEMM (validated): C[M,N] = A[M,768] @ W[768,N] + bias
// ===========================================================================
__global__ __launch_bounds__(256, 1)
void gemm_mma(const float* __restrict__ A, const float* __restrict__ W,
              const float* __restrict__ bias, float* __restrict__ C, int N)
{
    extern __shared__ float sm[];
    const uint32_t sbase = smem_u32(sm);
    const int tid  = threadIdx.x;
    const int lane = tid & 31, wid = tid >> 5;
    const int wm   = wid >> 2, wn = wid & 3;
    const int bm   = blockIdx.y * 128, bn = blockIdx.x * 128;

    float acc[4][4][4];
    #pragma unroll
    for (int mi = 0; mi < 4; mi++)
        #pragma unroll
        for (int ni = 0; ni < 4; ni++)
            #pragma unroll
            for (int r = 0; r < 4; r++) acc[mi][ni][r] = 0.f;

    int a_row[4], a_c0[4], b_k[4], b_n0[4];
    #pragma unroll
    for (int i = 0; i < 4; i++) {
        int idx = i * 256 + tid;
        a_row[i] = idx >> 3;
        a_c0[i]  = (idx & 7) * 4;
        b_k[i]   = idx >> 5;
        b_n0[i]  = (idx & 31) * 4;
    }

    float4 ga[4], gb[4];

    #define LOADG(c)                                                          \
        do {                                                                  \
            _Pragma("unroll")                                                 \
            for (int i = 0; i < 4; i++)                                       \
                ga[i] = *(const float4*)&A[(size_t)(bm + a_row[i]) * GK       \
                                           + (c) * 32 + a_c0[i]];             \
            _Pragma("unroll")                                                 \
            for (int i = 0; i < 4; i++)                                       \
                gb[i] = *(const float4*)&W[(size_t)((c) * 32 + b_k[i]) * N    \
                                           + bn + b_n0[i]];                   \
        } while (0)

    #define STORES(s)                                                         \
        do {                                                                  \
            const uint32_t sA = sbase + (uint32_t)(s) * 32768u;               \
            const uint32_t sB = sA + 16384u;                                  \
            _Pragma("unroll")                                                 \
            for (int i = 0; i < 4; i++) {                                     \
                int row = a_row[i], c0 = a_c0[i];                             \
                int kt = c0 >> 3, c8hi = (c0 & 4) >> 2;                       \
                int mt = row >> 4, r8 = row & 15;                             \
                uint32_t tb = (uint32_t)((kt * 8 + mt) << 9);                 \
                uint32_t sw = (uint32_t)((kt << 5) ^ ((r8 & 2) << 3));        \
                uint32_t reg = (uint32_t)((r8 >> 3) + 2 * c8hi);              \
                float v[4] = {ga[i].x, ga[i].y, ga[i].z, ga[i].w};            \
                _Pragma("unroll")                                             \
                for (int j = 0; j < 4; j++) {                                 \
                    uint32_t ln = (uint32_t)(((r8 & 7) * 4 + j));             \
                    uint32_t off = (tb + (ln << 4) + (reg << 2)) ^ sw;        \
                    asm volatile("st.shared.b32 [%0], %1;"                    \
                                 :: "r"(sA + off), "r"(f2tf32(v[j]))          \
                                 : "memory");                                 \
                }                                                             \
            }                                                                 \
            _Pragma("unroll")                                                 \
            for (int i = 0; i < 4; i++) {                                     \
                int k = b_k[i], n0 = b_n0[i];                                 \
                int kt = k >> 3, k8 = k & 7;                                  \
                uint32_t reg = (uint32_t)(k8 >> 2);                           \
                uint32_t k3  = (uint32_t)(k8 & 3);                            \
                float v[4] = {gb[i].x, gb[i].y, gb[i].z, gb[i].w};            \
                _Pragma("unroll")                                             \
                for (int j = 0; j < 4; j++) {                                 \
                    int n = n0 + j, nt = n >> 3, n8 = n & 7;                  \
                    uint32_t off = (uint32_t)(((kt * 16 + nt) << 8)           \
                                 + ((n8 * 4 + (int)k3) << 3) + (reg << 2));   \
                    off ^= (uint32_t)(nt << 3);                               \
                    asm volatile("st.shared.b32 [%0], %1;"                    \
                                 :: "r"(sB + off), "r"(f2tf32(v[j]))          \
                                 : "memory");                                 \
                }                                                             \
            }                                                                 \
        } while (0)

    LOADG(0);
    STORES(0);
    __syncthreads();

    for (int c = 0; c < NCHUNK; c++) {
        if (c + 1 < NCHUNK) LOADG(c + 1);

        const uint32_t sA = sbase + (uint32_t)(c & 1) * 32768u;
        const uint32_t sB = sA + 16384u;
        #pragma unroll
        for (int ks = 0; ks < 4; ks++) {
            uint32_t af[4][4], bf[4][2];
            #pragma unroll
            for (int mi = 0; mi < 4; mi++) {
                uint32_t off = (uint32_t)(((ks * 8 + wm * 4 + mi) << 9)
                             + (lane << 4));
                off ^= (uint32_t)((ks << 5) ^ ((lane & 8) << 1));
                asm volatile("ld.shared.v4.b32 {%0,%1,%2,%3}, [%4];"
                             : "=r"(af[mi][0]), "=r"(af[mi][1]),
                               "=r"(af[mi][2]), "=r"(af[mi][3])
                             : "r"(sA + off));
            }
            #pragma unroll
            for (int ni = 0; ni < 4; ni++) {
                int bnt = wn * 4 + ni;
                uint32_t off = (uint32_t)(((ks * 16 + bnt) << 8) + (lane << 3));
                off ^= (uint32_t)(bnt << 3);
                asm volatile("ld.shared.v2.b32 {%0,%1}, [%2];"
                             : "=r"(bf[ni][0]), "=r"(bf[ni][1])
                             : "r"(sB + off));
            }
            #pragma unroll
            for (int mi = 0; mi < 4; mi++)
                #pragma unroll
                for (int ni = 0; ni < 4; ni++)
                    mma_tf32(acc[mi][ni], af[mi], bf[ni]);
        }

        if (c + 1 < NCHUNK) STORES((c + 1) & 1);
        __syncthreads();
    }

    #pragma unroll
    for (int mi = 0; mi < 4; mi++) {
        int row = bm + wm * 64 + mi * 16 + (lane >> 2);
        #pragma unroll
        for (int ni = 0; ni < 4; ni++) {
            int col = bn + wn * 32 + ni * 8 + (lane & 3) * 2;
            float2 bb = *(const float2*)&bias[col];
            float2 o0, o1;
            o0.x = acc[mi][ni][0] + bb.x;
            o0.y = acc[mi][ni][1] + bb.y;
            o1.x = acc[mi][ni][2] + bb.x;
            o1.y = acc[mi][ni][3] + bb.y;
            *(float2*)&C[(size_t)row * N + col]       = o0;
            *(float2*)&C[(size_t)(row + 8) * N + col] = o1;
        }
    }
    #undef LOADG
    #undef STORES
}

// ===========================================================================
// K/V -> fragment-native tf32 conversion, once per (b,h,kv-tile).
// ===========================================================================
__global__ __launch_bounds__(128)
void conv_kv()
{
    const int tid = threadIdx.x;
    const int bh  = blockIdx.y;
    const int kt  = blockIdx.x;
    const int b   = bh / NHEADS;
    const int h   = bh % NHEADS;

    const float* base = g_qkv + (size_t)b * SEQ * QKVN + h * HD;
    uint32_t* out = g_kvf + ((size_t)bh * 16 + kt) * 8192;

    // ---- K tile (b-frag native for QK^T: n=kv, k=hd) ----
    {
        const int krr = tid >> 4, kd0 = (tid & 15) * 4;
        const float* Kg = base + DIM + (size_t)(kt * 64) * QKVN;
        float4 t[8];
        #pragma unroll
        for (int p = 0; p < 8; p++)
            t[p] = *(const float4*)(Kg + (size_t)(p * 8 + krr) * QKVN + kd0);
        #pragma unroll
        for (int p = 0; p < 8; p++) {
            int r = p * 8 + krr;
            float v[4] = {t[p].x, t[p].y, t[p].z, t[p].w};
            #pragma unroll
            for (int e = 0; e < 4; e++) {
                int d = kd0 + e;
                uint32_t ln   = (uint32_t)(((r & 7) << 2) | (d & 3));
                uint32_t word = (uint32_t)(((r >> 3) * 8 + (d >> 3)) << 6)
                              + ((ln * 2u + (uint32_t)((d >> 2) & 1))
                                 ^ (uint32_t)((d >> 3) << 2));
                out[word] = f2tf32(v[e]);
            }
        }
    }
    // ---- V^T tile (b-frag native for PV: n=hd, k=kv) ----
    {
        const int vrr = tid & 31, vd0 = (tid >> 5) * 4;
        const float* Vg = base + 2 * DIM + (size_t)(kt * 64) * QKVN;
        float4 t[8];
        #pragma unroll
        for (int p = 0; p < 8; p++) {
            int r  = (p & 1) * 32 + vrr;
            int d0 = (p >> 1) * 16 + vd0;
            t[p] = *(const float4*)(Vg + (size_t)r * QKVN + d0);
        }
        #pragma unroll
        for (int p = 0; p < 8; p++) {
            int r  = (p & 1) * 32 + vrr;
            int d0 = (p >> 1) * 16 + vd0;
            float v[4] = {t[p].x, t[p].y, t[p].z, t[p].w};
            #pragma unroll
            for (int e = 0; e < 4; e++) {
                int d = d0 + e;
                uint32_t ln   = (uint32_t)(((d & 7) << 2) | (r & 3));
                uint32_t word = (uint32_t)(((d >> 3) * 8 + (r >> 3)) << 6)
                              + ((ln * 2u + (uint32_t)((r >> 2) & 1))
                                 ^ (uint32_t)((r >> 3) << 2));
                out[4096 + word] = f2tf32(v[e]);
            }
        }
    }
}

// ===========================================================================
// Tensor-core flash attention: cp.async double-buffered K|V tiles.
// CTA = (b, h, 64-q tile), 128 threads. SMEM: buf0 32K | buf1 32K | Ps 16K.
// ===========================================================================
__global__ __launch_bounds__(128)
void attn_mma()
{
    extern __shared__ uint32_t smu[];
    const uint32_t sb  = smem_u32(smu);
    const uint32_t PsB = sb + 65536u;

    const int tid  = threadIdx.x;
    const int lane = tid & 31, w = tid >> 5;
    const int bh   = blockIdx.y;
    const int b    = bh / NHEADS;
    const int h    = bh % NHEADS;
    const int q0   = blockIdx.x * 64;

    const float* base = g_qkv + (size_t)b * SEQ * QKVN + h * HD;

    // ---- Q into registers as A-fragments (pre-scaled to exp2 domain) ----
    const int r0w = w * 16 + (lane >> 2);     // CTA-local q row (0..63)
    const int c0  = lane & 3;
    uint32_t qa[8][4];
    {
        const float* Qp0 = base + (size_t)(q0 + r0w) * QKVN;
        const float* Qp1 = Qp0 + 8 * QKVN;
        #pragma unroll
        for (int ks = 0; ks < 8; ks++) {
            qa[ks][0] = f2tf32(Qp0[ks * 8 + c0]     * SC2);
            qa[ks][1] = f2tf32(Qp1[ks * 8 + c0]     * SC2);
            qa[ks][2] = f2tf32(Qp0[ks * 8 + c0 + 4] * SC2);
            qa[ks][3] = f2tf32(Qp1[ks * 8 + c0 + 4] * SC2);
        }
    }

    float oacc[8][4];
    #pragma unroll
    for (int nt = 0; nt < 8; nt++)
        #pragma unroll
        for (int r = 0; r < 4; r++) oacc[nt][r] = 0.f;
    float m0 = -INFINITY, m1 = -INFINITY, l0 = 0.f, l1 = 0.f;

    // P-store positions (per lane constants)
    const int cc0 = 2 * c0, cc1 = cc0 + 1;
    const uint32_t pos0 = (uint32_t)((cc0 & 3) * 2 + (cc0 >> 2));
    const uint32_t pos1 = (uint32_t)((cc1 & 3) * 2 + (cc1 >> 2));
    const uint32_t swz  = (uint32_t)((r0w & 3) << 3);
    const uint32_t prow0 = PsB + (uint32_t)r0w * 256u;
    const uint32_t prow1 = prow0 + 8u * 256u;

    const uint4* kvsrc = (const uint4*)(g_kvf + (size_t)bh * 16 * 8192);

    // prologue: async-copy tile 0 into buf0
    {
        const uint4* src = kvsrc;
        #pragma unroll
        for (int i = 0; i < 16; i++) {
            int idx = i * 128 + tid;
            cp_async16(sb + (uint32_t)idx * 16u, src + idx);
        }
        asm volatile("cp.async.commit_group;" ::: "memory");
    }

    for (int kt = 0; kt < SEQ / 64; kt++) {
        // issue copy for tile kt+1 into the other buffer
        if (kt + 1 < SEQ / 64) {
            const uint4* src = kvsrc + (size_t)(kt + 1) * 2048;
            const uint32_t dst = sb + (uint32_t)((kt + 1) & 1) * 32768u;
            #pragma unroll
            for (int i = 0; i < 16; i++) {
                int idx = i * 128 + tid;
                cp_async16(dst + (uint32_t)idx * 16u, src + idx);
            }
            asm volatile("cp.async.commit_group;" ::: "memory");
            asm volatile("cp.async.wait_group 1;" ::: "memory");
        } else {
            asm volatile("cp.async.wait_group 0;" ::: "memory");
        }
        __syncthreads();   // tile kt visible to all warps

        const uint32_t KsB = sb + (uint32_t)(kt & 1) * 32768u;
        const uint32_t VsB = KsB + 16384u;

        // ---- S = Q K^T ----
        float sacc[8][4];
        #pragma unroll
        for (int nt = 0; nt < 8; nt++)
            #pragma unroll
            for (int r = 0; r < 4; r++) sacc[nt][r] = 0.f;

        #pragma unroll
        for (int ks = 0; ks < 8; ks++) {
            uint32_t bf[8][2];
            #pragma unroll
            for (int nt = 0; nt < 8; nt++) {
                uint32_t off = (uint32_t)((nt * 8 + ks) << 6)
                             + (((uint32_t)lane * 2u) ^ (uint32_t)(ks << 2));
                asm volatile("ld.shared.v2.b32 {%0,%1}, [%2];"
                             : "=r"(bf[nt][0]), "=r"(bf[nt][1])
                             : "r"(KsB + off * 4u));
            }
            #pragma unroll
            for (int nt = 0; nt < 8; nt++)
                mma_tf32(sacc[nt], qa[ks], bf[nt]);
        }

        // ---- online softmax (exp2 domain) ----
        float mx0 = -INFINITY, mx1 = -INFINITY;
        #pragma unroll
        for (int nt = 0; nt < 8; nt++) {
            mx0 = fmaxf(mx0, fmaxf(sacc[nt][0], sacc[nt][1]));
            mx1 = fmaxf(mx1, fmaxf(sacc[nt][2], sacc[nt][3]));
        }
        mx0 = fmaxf(mx0, __shfl_xor_sync(0xffffffffu, mx0, 1));
        mx0 = fmaxf(mx0, __shfl_xor_sync(0xffffffffu, mx0, 2));
        mx1 = fmaxf(mx1, __shfl_xor_sync(0xffffffffu, mx1, 1));
        mx1 = fmaxf(mx1, __shfl_xor_sync(0xffffffffu, mx1, 2));
        float mn0 = fmaxf(m0, mx0), mn1 = fmaxf(m1, mx1);
        float a0 = ex2(m0 - mn0), a1 = ex2(m1 - mn1);
        m0 = mn0; m1 = mn1;
        l0 *= a0;  l1 *= a1;

        float sum0 = 0.f, sum1 = 0.f;
        #pragma unroll
        for (int nt = 0; nt < 8; nt++) {
            float p00 = ex2(sacc[nt][0] - m0);
            float p01 = ex2(sacc[nt][1] - m0);
            float p10 = ex2(sacc[nt][2] - m1);
            float p11 = ex2(sacc[nt][3] - m1);
            sum0 += p00 + p01;
            sum1 += p10 + p11;
            oacc[nt][0] *= a0; oacc[nt][1] *= a0;
            oacc[nt][2] *= a1; oacc[nt][3] *= a1;
            uint32_t nb = (uint32_t)(nt * 8);
            asm volatile("st.shared.b32 [%0], %1;"
                         :: "r"(prow0 + ((nb + pos0) ^ swz) * 4u),
                            "r"(f2tf32(p00)) : "memory");
            asm volatile("st.shared.b32 [%0], %1;"
                         :: "r"(prow0 + ((nb + pos1) ^ swz) * 4u),
                            "r"(f2tf32(p01)) : "memory");
            asm volatile("st.shared.b32 [%0], %1;"
                         :: "r"(prow1 + ((nb + pos0) ^ swz) * 4u),
                            "r"(f2tf32(p10)) : "memory");
            asm volatile("st.shared.b32 [%0], %1;"
                         :: "r"(prow1 + ((nb + pos1) ^ swz) * 4u),
                            "r"(f2tf32(p11)) : "memory");
        }
        sum0 += __shfl_xor_sync(0xffffffffu, sum0, 1);
        sum0 += __shfl_xor_sync(0xffffffffu, sum0, 2);
        sum1 += __shfl_xor_sync(0xffffffffu, sum1, 1);
        sum1 += __shfl_xor_sync(0xffffffffu, sum1, 2);
        l0 += sum0; l1 += sum1;

        // ---- O += P V  (P rows are warp-private: no barrier needed) ----
        #pragma unroll
        for (int ks = 0; ks < 8; ks++) {
            uint32_t pa[4];
            uint32_t wo = (((uint32_t)(ks * 8 + c0 * 2)) ^ swz) * 4u;
            asm volatile("ld.shared.v2.b32 {%0,%1}, [%2];"
                         : "=r"(pa[0]), "=r"(pa[2]) : "r"(prow0 + wo));
            asm volatile("ld.shared.v2.b32 {%0,%1}, [%2];"
                         : "=r"(pa[1]), "=r"(pa[3]) : "r"(prow1 + wo));
            #pragma unroll
            for (int nt = 0; nt < 8; nt++) {
                uint32_t vb[2];
                uint32_t off = (uint32_t)((nt * 8 + ks) << 6)
                             + (((uint32_t)lane * 2u) ^ (uint32_t)(ks << 2));
                asm volatile("ld.shared.v2.b32 {%0,%1}, [%2];"
                             : "=r"(vb[0]), "=r"(vb[1]) : "r"(VsB + off * 4u));
                mma_tf32(oacc[nt], pa, vb);
            }
        }
        __syncthreads();   // all warps done with buf[kt&1] before refill at kt+2
    }

    // ---- normalize, write out [B*N, DIM] (col = h*64 + d) ----
    {
        float inv0 = 1.f / l0, inv1 = 1.f / l1;
        float* O0 = g_att + (size_t)(b * SEQ + q0 + r0w) * DIM + h * HD;
        float* O1 = O0 + 8 * DIM;
        #pragma unroll
        for (int nt = 0; nt < 8; nt++) {
            int col = nt * 8 + cc0;
            float2 v0 = {oacc[nt][0] * inv0, oacc[nt][1] * inv0};
            float2 v1 = {oacc[nt][2] * inv1, oacc[nt][3] * inv1};
            *(float2*)(O0 + col) = v0;
            *(float2*)(O1 + col) = v1;
        }
    }
}

// ---------------------------------------------------------------------------
extern "C" void kernel_launch(void* const* d_in, const int* in_sizes, int n_in,
                              void* d_out, int out_size)
{
    const float* x      = (const float*)d_in[0];
    const float* w_qkv  = (const float*)d_in[1];
    const float* b_qkv  = (const float*)d_in[2];
    const float* w_proj = (const float*)d_in[3];
    const float* b_proj = (const float*)d_in[4];
    float* out = (float*)d_out;

    float* qkv = nullptr;
    float* att = nullptr;
    cudaGetSymbolAddress((void**)&qkv, g_qkv);
    cudaGetSymbolAddress((void**)&att, g_att);

    const int gemm_smem = 65536;
    const int attn_smem = 81920;   // 2x32K K|V buffers + 16K Ps
    cudaFuncSetAttribute(gemm_mma,
                         cudaFuncAttributeMaxDynamicSharedMemorySize, gemm_smem);
    cudaFuncSetAttribute(attn_mma,
                         cudaFuncAttributeMaxDynamicSharedMemorySize, attn_smem);

    // 1) QKV projection: [8192,768] @ [768,2304] + bias   (tf32 mma.sync)
    gemm_mma<<<dim3(QKVN / 128, MROWS / 128), 256, gemm_smem>>>(
        x, w_qkv, b_qkv, qkv, QKVN);

    // 2a) One-time K/V fragment-layout conversion
    conv_kv<<<dim3(16, BATCH * NHEADS), 128>>>();

    // 2b) Tensor-core flash attention (cp.async double-buffered)
    attn_mma<<<dim3(SEQ / 64, BATCH * NHEADS), 128, attn_smem>>>();

    // 3) Output projection: [8192,768] @ [768,768] + bias (tf32 mma.sync)
    gemm_mma<<<dim3(DIM / 128, MROWS / 128), 256, gemm_smem>>>(
        att, w_proj, b_proj, out, DIM);
}

// round 9
// speedup vs baseline: 1.3671x; 1.0463x over previous
#include <cuda_runtime.h>
#include <math.h>
#include <stdint.h>

#define DIM     768
#define NHEADS  12
#define HD      64
#define BATCH   8
#define SEQ     1024
#define MROWS   (BATCH*SEQ)     /* 8192 */
#define QKVN    (3*DIM)         /* 2304 */
#define SC2     0.1803368801111244f   /* 64^-0.5 * log2(e) */
#define GK      768
#define NCHUNK  24

// Scratch (allocation-free rule: __device__ globals)
__device__ __align__(1024) float    g_qkv[(size_t)MROWS * QKVN];  // [B*N, 3*DIM]
__device__ __align__(1024) float    g_att[(size_t)MROWS * DIM];   // [B*N, DIM]
__device__ __align__(1024) uint32_t g_kvf[(size_t)BATCH * NHEADS * 16 * 8192];
// fragment-native tf32 operand scratch for the GEMMs:
__device__ __align__(1024) uint32_t g_xf [(size_t)64 * NCHUNK * 4096];  // x    A-frags
__device__ __align__(1024) uint32_t g_af2[(size_t)64 * NCHUNK * 4096];  // att  A-frags
__device__ __align__(1024) uint32_t g_wqf[(size_t)18 * NCHUNK * 4096];  // Wqkv B-frags
__device__ __align__(1024) uint32_t g_wpf[(size_t) 6 * NCHUNK * 4096];  // Wprj B-frags

__device__ __forceinline__ uint32_t smem_u32(const void* p) {
    uint32_t a;
    asm("{ .reg .u64 t; cvta.to.shared.u64 t, %1; cvt.u32.u64 %0, t; }"
        : "=r"(a) : "l"(p));
    return a;
}
__device__ __forceinline__ uint32_t f2tf32(float f) {
    uint32_t u;
    asm("cvt.rna.tf32.f32 %0, %1;" : "=r"(u) : "f"(f));
    return u;
}
__device__ __forceinline__ float ex2(float x) {
    float r;
    asm("ex2.approx.ftz.f32 %0, %1;" : "=f"(r) : "f"(x));
    return r;
}
__device__ __forceinline__ void mma_tf32(float* c, const uint32_t* a,
                                         const uint32_t* b) {
    asm volatile(
        "mma.sync.aligned.m16n8k8.row.col.f32.tf32.tf32.f32 "
        "{%0,%1,%2,%3}, {%4,%5,%6,%7}, {%8,%9}, {%0,%1,%2,%3};"
        : "+f"(c[0]), "+f"(c[1]), "+f"(c[2]), "+f"(c[3])
        : "r"(a[0]), "r"(a[1]), "r"(a[2]), "r"(a[3]), "r"(b[0]), "r"(b[1]));
}
__device__ __forceinline__ void cp_async16(uint32_t dst, const void* src) {
    asm volatile("cp.async.cg.shared.global [%0], [%1], 16;"
                 :: "r"(dst), "l"(src) : "memory");
}

// ===========================================================================
// conv_a: A[M,768] float -> A-fragment-native tf32 blocks.
// out[(rb*24 + chunk)*4096 + word], word formulas identical to validated
// GEMM STORES-A. grid (M/128, 8), 256 thr.
// ===========================================================================
__global__ __launch_bounds__(256)
void conv_a(const float* __restrict__ A, uint32_t* __restrict__ out)
{
    const int rb = blockIdx.x;
    const float* Ab = A + (size_t)rb * 128 * GK;
    uint32_t* o = out + (size_t)rb * NCHUNK * 4096;

    #pragma unroll
    for (int i = 0; i < 12; i++) {
        int idx = threadIdx.x + (blockIdx.y * 12 + i) * 256;   // 0..24575
        int row = idx / 192;
        int col = (idx % 192) * 4;
        int chunk = col >> 5, c0 = col & 31;
        float4 v = *(const float4*)(Ab + (size_t)row * GK + col);
        int kt = c0 >> 3, c8hi = (c0 & 4) >> 2;
        int r8 = row & 15, mt = row >> 4;
        uint32_t tb  = (uint32_t)((kt * 8 + mt) << 9);
        uint32_t sw  = (uint32_t)((kt << 5) ^ ((r8 & 2) << 3));
        uint32_t reg = (uint32_t)((r8 >> 3) + 2 * c8hi);
        float vv[4] = {v.x, v.y, v.z, v.w};
        uint32_t* oc = o + chunk * 4096;
        #pragma unroll
        for (int j = 0; j < 4; j++) {
            uint32_t ln  = (uint32_t)((r8 & 7) * 4 + j);
            uint32_t off = (tb + (ln << 4) + (reg << 2)) ^ sw;
            oc[off >> 2] = f2tf32(vv[j]);
        }
    }
}

// ===========================================================================
// conv_b: W[768,N] float -> B-fragment-native tf32 blocks.
// out[(cb*24 + chunk)*4096 + word], formulas identical to GEMM STORES-B.
// grid (N/128, 8), 256 thr.
// ===========================================================================
__global__ __launch_bounds__(256)
void conv_b(const float* __restrict__ W, uint32_t* __restrict__ out, int N)
{
    const int cb = blockIdx.x;
    const int bn = cb * 128;
    uint32_t* o = out + (size_t)cb * NCHUNK * 4096;

    #pragma unroll
    for (int i = 0; i < 12; i++) {
        int idx = threadIdx.x + (blockIdx.y * 12 + i) * 256;   // 0..24575
        int k  = idx >> 5;              // 0..767
        int n0 = (idx & 31) << 2;       // 0..124
        float4 v = *(const float4*)(W + (size_t)k * N + bn + n0);
        int chunk = k >> 5, kl = k & 31;
        int kt = kl >> 3, k8 = kl & 7;
        uint32_t reg = (uint32_t)(k8 >> 2);
        uint32_t k3  = (uint32_t)(k8 & 3);
        float vv[4] = {v.x, v.y, v.z, v.w};
        uint32_t* oc = o + chunk * 4096;
        #pragma unroll
        for (int j = 0; j < 4; j++) {
            int n = n0 + j, nt = n >> 3, n8 = n & 7;
            uint32_t off = (uint32_t)(((kt * 16 + nt) << 8)
                         + ((n8 * 4 + (int)k3) << 3) + (reg << 2));
            off ^= (uint32_t)(nt << 3);
            oc[off >> 2] = f2tf32(vv[j]);
        }
    }
}

// ===========================================================================
// gemm2: pre-converted-operand tf32 GEMM. cp.async double-buffered,
// no cvt/scatter in-loop -> low regs -> 2 CTAs/SM.
// C[M,N] = Af-blocks @ Bf-blocks + bias.
// smem: buf s (s=0,1): A 16KB | B 16KB  (64 KB total)
// ===========================================================================
__global__ __launch_bounds__(256, 2)
void gemm2(const uint32_t* __restrict__ Af, const uint32_t* __restrict__ Bf,
           const float* __restrict__ bias, float* __restrict__ C, int N)
{
    extern __shared__ uint32_t sm2[];
    const uint32_t sbase = smem_u32(sm2);
    const int tid  = threadIdx.x;
    const int lane = tid & 31, wid = tid >> 5;
    const int wm   = wid >> 2, wn = wid & 3;
    const int bm   = blockIdx.y * 128, bn = blockIdx.x * 128;

    const uint4* Ab = (const uint4*)(Af + (size_t)blockIdx.y * NCHUNK * 4096);
    const uint4* Bb = (const uint4*)(Bf + (size_t)blockIdx.x * NCHUNK * 4096);

    float acc[4][4][4];
    #pragma unroll
    for (int mi = 0; mi < 4; mi++)
        #pragma unroll
        for (int ni = 0; ni < 4; ni++)
            #pragma unroll
            for (int r = 0; r < 4; r++) acc[mi][ni][r] = 0.f;

    #define COPYC(c, s)                                                       \
        do {                                                                  \
            const uint32_t dA = sbase + (uint32_t)(s) * 32768u;               \
            const uint32_t dB = dA + 16384u;                                  \
            const uint4* sa = Ab + (c) * 1024;                                \
            const uint4* sbp = Bb + (c) * 1024;                               \
            _Pragma("unroll")                                                 \
            for (int i = 0; i < 4; i++) {                                     \
                int idx = tid + i * 256;                                      \
                cp_async16(dA + (uint32_t)idx * 16u, sa + idx);               \
                cp_async16(dB + (uint32_t)idx * 16u, sbp + idx);              \
            }                                                                 \
            asm volatile("cp.async.commit_group;" ::: "memory");              \
        } while (0)

    COPYC(0, 0);

    for (int c = 0; c < NCHUNK; c++) {
        if (c + 1 < NCHUNK) {
            COPYC(c + 1, (c + 1) & 1);
            asm volatile("cp.async.wait_group 1;" ::: "memory");
        } else {
            asm volatile("cp.async.wait_group 0;" ::: "memory");
        }
        __syncthreads();

        const uint32_t sA = sbase + (uint32_t)(c & 1) * 32768u;
        const uint32_t sB = sA + 16384u;
        #pragma unroll
        for (int ks = 0; ks < 4; ks++) {
            uint32_t af[4][4], bf[4][2];
            #pragma unroll
            for (int mi = 0; mi < 4; mi++) {
                uint32_t off = (uint32_t)(((ks * 8 + wm * 4 + mi) << 9)
                             + (lane << 4));
                off ^= (uint32_t)((ks << 5) ^ ((lane & 8) << 1));
                asm volatile("ld.shared.v4.b32 {%0,%1,%2,%3}, [%4];"
                             : "=r"(af[mi][0]), "=r"(af[mi][1]),
                               "=r"(af[mi][2]), "=r"(af[mi][3])
                             : "r"(sA + off));
            }
            #pragma unroll
            for (int ni = 0; ni < 4; ni++) {
                int bnt = wn * 4 + ni;
                uint32_t off = (uint32_t)(((ks * 16 + bnt) << 8) + (lane << 3));
                off ^= (uint32_t)(bnt << 3);
                asm volatile("ld.shared.v2.b32 {%0,%1}, [%2];"
                             : "=r"(bf[ni][0]), "=r"(bf[ni][1])
                             : "r"(sB + off));
            }
            #pragma unroll
            for (int mi = 0; mi < 4; mi++)
                #pragma unroll
                for (int ni = 0; ni < 4; ni++)
                    mma_tf32(acc[mi][ni], af[mi], bf[ni]);
        }
        __syncthreads();
    }

    #pragma unroll
    for (int mi = 0; mi < 4; mi++) {
        int row = bm + wm * 64 + mi * 16 + (lane >> 2);
        #pragma unroll
        for (int ni = 0; ni < 4; ni++) {
            int col = bn + wn * 32 + ni * 8 + (lane & 3) * 2;
            float2 bb = *(const float2*)&bias[col];
            float2 o0, o1;
            o0.x = acc[mi][ni][0] + bb.x;
            o0.y = acc[mi][ni][1] + bb.y;
            o1.x = acc[mi][ni][2] + bb.x;
            o1.y = acc[mi][ni][3] + bb.y;
            *(float2*)&C[(size_t)row * N + col]       = o0;
            *(float2*)&C[(size_t)(row + 8) * N + col] = o1;
        }
    }
    #undef COPYC
}

// ===========================================================================
// K/V -> fragment-native tf32 conversion, once per (b,h,kv-tile).
// ===========================================================================
__global__ __launch_bounds__(128)
void conv_kv()
{
    const int tid = threadIdx.x;
    const int bh  = blockIdx.y;
    const int kt  = blockIdx.x;
    const int b   = bh / NHEADS;
    const int h   = bh % NHEADS;

    const float* base = g_qkv + (size_t)b * SEQ * QKVN + h * HD;
    uint32_t* out = g_kvf + ((size_t)bh * 16 + kt) * 8192;

    {
        const int krr = tid >> 4, kd0 = (tid & 15) * 4;
        const float* Kg = base + DIM + (size_t)(kt * 64) * QKVN;
        float4 t[8];
        #pragma unroll
        for (int p = 0; p < 8; p++)
            t[p] = *(const float4*)(Kg + (size_t)(p * 8 + krr) * QKVN + kd0);
        #pragma unroll
        for (int p = 0; p < 8; p++) {
            int r = p * 8 + krr;
            float v[4] = {t[p].x, t[p].y, t[p].z, t[p].w};
            #pragma unroll
            for (int e = 0; e < 4; e++) {
                int d = kd0 + e;
                uint32_t ln   = (uint32_t)(((r & 7) << 2) | (d & 3));
                uint32_t word = (uint32_t)(((r >> 3) * 8 + (d >> 3)) << 6)
                              + ((ln * 2u + (uint32_t)((d >> 2) & 1))
                                 ^ (uint32_t)((d >> 3) << 2));
                out[word] = f2tf32(v[e]);
            }
        }
    }
    {
        const int vrr = tid & 31, vd0 = (tid >> 5) * 4;
        const float* Vg = base + 2 * DIM + (size_t)(kt * 64) * QKVN;
        float4 t[8];
        #pragma unroll
        for (int p = 0; p < 8; p++) {
            int r  = (p & 1) * 32 + vrr;
            int d0 = (p >> 1) * 16 + vd0;
            t[p] = *(const float4*)(Vg + (size_t)r * QKVN + d0);
        }
        #pragma unroll
        for (int p = 0; p < 8; p++) {
            int r  = (p & 1) * 32 + vrr;
            int d0 = (p >> 1) * 16 + vd0;
            float v[4] = {t[p].x, t[p].y, t[p].z, t[p].w};
            #pragma unroll
            for (int e = 0; e < 4; e++) {
                int d = d0 + e;
                uint32_t ln   = (uint32_t)(((d & 7) << 2) | (r & 3));
                uint32_t word = (uint32_t)(((d >> 3) * 8 + (r >> 3)) << 6)
                              + ((ln * 2u + (uint32_t)((r >> 2) & 1))
                                 ^ (uint32_t)((r >> 3) << 2));
                out[4096 + word] = f2tf32(v[e]);
            }
        }
    }
}

// ===========================================================================
// Tensor-core flash attention (round-8 winner, unchanged).
// ===========================================================================
__global__ __launch_bounds__(128)
void attn_mma()
{
    extern __shared__ uint32_t smu[];
    const uint32_t sb  = smem_u32(smu);
    const uint32_t PsB = sb + 65536u;

    const int tid  = threadIdx.x;
    const int lane = tid & 31, w = tid >> 5;
    const int bh   = blockIdx.y;
    const int b    = bh / NHEADS;
    const int h    = bh % NHEADS;
    const int q0   = blockIdx.x * 64;

    const float* base = g_qkv + (size_t)b * SEQ * QKVN + h * HD;

    const int r0w = w * 16 + (lane >> 2);
    const int c0  = lane & 3;
    uint32_t qa[8][4];
    {
        const float* Qp0 = base + (size_t)(q0 + r0w) * QKVN;
        const float* Qp1 = Qp0 + 8 * QKVN;
        #pragma unroll
        for (int ks = 0; ks < 8; ks++) {
            qa[ks][0] = f2tf32(Qp0[ks * 8 + c0]     * SC2);
            qa[ks][1] = f2tf32(Qp1[ks * 8 + c0]     * SC2);
            qa[ks][2] = f2tf32(Qp0[ks * 8 + c0 + 4] * SC2);
            qa[ks][3] = f2tf32(Qp1[ks * 8 + c0 + 4] * SC2);
        }
    }

    float oacc[8][4];
    #pragma unroll
    for (int nt = 0; nt < 8; nt++)
        #pragma unroll
        for (int r = 0; r < 4; r++) oacc[nt][r] = 0.f;
    float m0 = -INFINITY, m1 = -INFINITY, l0 = 0.f, l1 = 0.f;

    const int cc0 = 2 * c0, cc1 = cc0 + 1;
    const uint32_t pos0 = (uint32_t)((cc0 & 3) * 2 + (cc0 >> 2));
    const uint32_t pos1 = (uint32_t)((cc1 & 3) * 2 + (cc1 >> 2));
    const uint32_t swz  = (uint32_t)((r0w & 3) << 3);
    const uint32_t prow0 = PsB + (uint32_t)r0w * 256u;
    const uint32_t prow1 = prow0 + 8u * 256u;

    const uint4* kvsrc = (const uint4*)(g_kvf + (size_t)bh * 16 * 8192);

    {
        const uint4* src = kvsrc;
        #pragma unroll
        for (int i = 0; i < 16; i++) {
            int idx = i * 128 + tid;
            cp_async16(sb + (uint32_t)idx * 16u, src + idx);
        }
        asm volatile("cp.async.commit_group;" ::: "memory");
    }

    for (int kt = 0; kt < SEQ / 64; kt++) {
        if (kt + 1 < SEQ / 64) {
            const uint4* src = kvsrc + (size_t)(kt + 1) * 2048;
            const uint32_t dst = sb + (uint32_t)((kt + 1) & 1) * 32768u;
            #pragma unroll
            for (int i = 0; i < 16; i++) {
                int idx = i * 128 + tid;
                cp_async16(dst + (uint32_t)idx * 16u, src + idx);
            }
            asm volatile("cp.async.commit_group;" ::: "memory");
            asm volatile("cp.async.wait_group 1;" ::: "memory");
        } else {
            asm volatile("cp.async.wait_group 0;" ::: "memory");
        }
        __syncthreads();

        const uint32_t KsB = sb + (uint32_t)(kt & 1) * 32768u;
        const uint32_t VsB = KsB + 16384u;

        float sacc[8][4];
        #pragma unroll
        for (int nt = 0; nt < 8; nt++)
            #pragma unroll
            for (int r = 0; r < 4; r++) sacc[nt][r] = 0.f;

        #pragma unroll
        for (int ks = 0; ks < 8; ks++) {
            uint32_t bf[8][2];
            #pragma unroll
            for (int nt = 0; nt < 8; nt++) {
                uint32_t off = (uint32_t)((nt * 8 + ks) << 6)
                             + (((uint32_t)lane * 2u) ^ (uint32_t)(ks << 2));
                asm volatile("ld.shared.v2.b32 {%0,%1}, [%2];"
                             : "=r"(bf[nt][0]), "=r"(bf[nt][1])
                             : "r"(KsB + off * 4u));
            }
            #pragma unroll
            for (int nt = 0; nt < 8; nt++)
                mma_tf32(sacc[nt], qa[ks], bf[nt]);
        }

        float mx0 = -INFINITY, mx1 = -INFINITY;
        #pragma unroll
        for (int nt = 0; nt < 8; nt++) {
            mx0 = fmaxf(mx0, fmaxf(sacc[nt][0], sacc[nt][1]));
            mx1 = fmaxf(mx1, fmaxf(sacc[nt][2], sacc[nt][3]));
        }
        mx0 = fmaxf(mx0, __shfl_xor_sync(0xffffffffu, mx0, 1));
        mx0 = fmaxf(mx0, __shfl_xor_sync(0xffffffffu, mx0, 2));
        mx1 = fmaxf(mx1, __shfl_xor_sync(0xffffffffu, mx1, 1));
        mx1 = fmaxf(mx1, __shfl_xor_sync(0xffffffffu, mx1, 2));
        float mn0 = fmaxf(m0, mx0), mn1 = fmaxf(m1, mx1);
        float a0 = ex2(m0 - mn0), a1 = ex2(m1 - mn1);
        m0 = mn0; m1 = mn1;
        l0 *= a0;  l1 *= a1;

        float sum0 = 0.f, sum1 = 0.f;
        #pragma unroll
        for (int nt = 0; nt < 8; nt++) {
            float p00 = ex2(sacc[nt][0] - m0);
            float p01 = ex2(sacc[nt][1] - m0);
            float p10 = ex2(sacc[nt][2] - m1);
            float p11 = ex2(sacc[nt][3] - m1);
            sum0 += p00 + p01;
            sum1 += p10 + p11;
            oacc[nt][0] *= a0; oacc[nt][1] *= a0;
            oacc[nt][2] *= a1; oacc[nt][3] *= a1;
            uint32_t nb = (uint32_t)(nt * 8);
            asm volatile("st.shared.b32 [%0], %1;"
                         :: "r"(prow0 + ((nb + pos0) ^ swz) * 4u),
                            "r"(f2tf32(p00)) : "memory");
            asm volatile("st.shared.b32 [%0], %1;"
                         :: "r"(prow0 + ((nb + pos1) ^ swz) * 4u),
                            "r"(f2tf32(p01)) : "memory");
            asm volatile("st.shared.b32 [%0], %1;"
                         :: "r"(prow1 + ((nb + pos0) ^ swz) * 4u),
                            "r"(f2tf32(p10)) : "memory");
            asm volatile("st.shared.b32 [%0], %1;"
                         :: "r"(prow1 + ((nb + pos1) ^ swz) * 4u),
                            "r"(f2tf32(p11)) : "memory");
        }
        sum0 += __shfl_xor_sync(0xffffffffu, sum0, 1);
        sum0 += __shfl_xor_sync(0xffffffffu, sum0, 2);
        sum1 += __shfl_xor_sync(0xffffffffu, sum1, 1);
        sum1 += __shfl_xor_sync(0xffffffffu, sum1, 2);
        l0 += sum0; l1 += sum1;

        #pragma unroll
        for (int ks = 0; ks < 8; ks++) {
            uint32_t pa[4];
            uint32_t wo = (((uint32_t)(ks * 8 + c0 * 2)) ^ swz) * 4u;
            asm volatile("ld.shared.v2.b32 {%0,%1}, [%2];"
                         : "=r"(pa[0]), "=r"(pa[2]) : "r"(prow0 + wo));
            asm volatile("ld.shared.v2.b32 {%0,%1}, [%2];"
                         : "=r"(pa[1]), "=r"(pa[3]) : "r"(prow1 + wo));
            #pragma unroll
            for (int nt = 0; nt < 8; nt++) {
                uint32_t vb[2];
                uint32_t off = (uint32_t)((nt * 8 + ks) << 6)
                             + (((uint32_t)lane * 2u) ^ (uint32_t)(ks << 2));
                asm volatile("ld.shared.v2.b32 {%0,%1}, [%2];"
                             : "=r"(vb[0]), "=r"(vb[1]) : "r"(VsB + off * 4u));
                mma_tf32(oacc[nt], pa, vb);
            }
        }
        __syncthreads();
    }

    {
        float inv0 = 1.f / l0, inv1 = 1.f / l1;
        float* O0 = g_att + (size_t)(b * SEQ + q0 + r0w) * DIM + h * HD;
        float* O1 = O0 + 8 * DIM;
        #pragma unroll
        for (int nt = 0; nt < 8; nt++) {
            int col = nt * 8 + cc0;
            float2 v0 = {oacc[nt][0] * inv0, oacc[nt][1] * inv0};
            float2 v1 = {oacc[nt][2] * inv1, oacc[nt][3] * inv1};
            *(float2*)(O0 + col) = v0;
            *(float2*)(O1 + col) = v1;
        }
    }
}

// ---------------------------------------------------------------------------
extern "C" void kernel_launch(void* const* d_in, const int* in_sizes, int n_in,
                              void* d_out, int out_size)
{
    const float* x      = (const float*)d_in[0];
    const float* w_qkv  = (const float*)d_in[1];
    const float* b_qkv  = (const float*)d_in[2];
    const float* w_proj = (const float*)d_in[3];
    const float* b_proj = (const float*)d_in[4];
    float* out = (float*)d_out;

    float *qkv = nullptr, *att = nullptr;
    uint32_t *xf = nullptr, *af2 = nullptr, *wqf = nullptr, *wpf = nullptr;
    cudaGetSymbolAddress((void**)&qkv, g_qkv);
    cudaGetSymbolAddress((void**)&att, g_att);
    cudaGetSymbolAddress((void**)&xf,  g_xf);
    cudaGetSymbolAddress((void**)&af2, g_af2);
    cudaGetSymbolAddress((void**)&wqf, g_wqf);
    cudaGetSymbolAddress((void**)&wpf, g_wpf);

    const int gemm_smem = 65536;
    const int attn_smem = 81920;
    cudaFuncSetAttribute(gemm2,
                         cudaFuncAttributeMaxDynamicSharedMemorySize, gemm_smem);
    cudaFuncSetAttribute(attn_mma,
                         cudaFuncAttributeMaxDynamicSharedMemorySize, attn_smem);

    // 0) operand conversions (x, weights)
    conv_a<<<dim3(64, 8), 256>>>(x, xf);
    conv_b<<<dim3(18, 8), 256>>>(w_qkv, wqf, QKVN);
    conv_b<<<dim3(6, 8),  256>>>(w_proj, wpf, DIM);

    // 1) QKV projection (pre-converted operands, cp.async pipeline)
    gemm2<<<dim3(QKVN / 128, MROWS / 128), 256, gemm_smem>>>(
        xf, wqf, b_qkv, qkv, QKVN);

    // 2) attention
    conv_kv<<<dim3(16, BATCH * NHEADS), 128>>>();
    attn_mma<<<dim3(SEQ / 64, BATCH * NHEADS), 128, attn_smem>>>();

    // 3) output projection
    conv_a<<<dim3(64, 8), 256>>>(att, af2);
    gemm2<<<dim3(DIM / 128, MROWS / 128), 256, gemm_smem>>>(
        af2, wpf, b_proj, out, DIM);
}

// round 10
// speedup vs baseline: 1.3834x; 1.0119x over previous
#include <cuda_runtime.h>
#include <math.h>
#include <stdint.h>

#define DIM     768
#define NHEADS  12
#define HD      64
#define BATCH   8
#define SEQ     1024
#define MROWS   (BATCH*SEQ)     /* 8192 */
#define QKVN    (3*DIM)         /* 2304 */
#define SC2     0.1803368801111244f   /* 64^-0.5 * log2(e) */
#define GK      768
#define NCHUNK  24

// Scratch (allocation-free rule: __device__ globals)
__device__ __align__(1024) float    g_qkv[(size_t)MROWS * QKVN];  // [B*N, 3*DIM]
__device__ __align__(1024) float    g_att[(size_t)MROWS * DIM];   // [B*N, DIM]
__device__ __align__(1024) uint32_t g_kvf[(size_t)BATCH * NHEADS * 16 * 8192];
// fragment-native tf32 operand scratch for the GEMMs:
__device__ __align__(1024) uint32_t g_xf [(size_t)64 * NCHUNK * 4096];  // x    A-frags
__device__ __align__(1024) uint32_t g_af2[(size_t)64 * NCHUNK * 4096];  // att  A-frags
__device__ __align__(1024) uint32_t g_wqf[(size_t)18 * NCHUNK * 4096];  // Wqkv B-frags
__device__ __align__(1024) uint32_t g_wpf[(size_t) 6 * NCHUNK * 4096];  // Wprj B-frags

__device__ __forceinline__ uint32_t smem_u32(const void* p) {
    uint32_t a;
    asm("{ .reg .u64 t; cvta.to.shared.u64 t, %1; cvt.u32.u64 %0, t; }"
        : "=r"(a) : "l"(p));
    return a;
}
__device__ __forceinline__ uint32_t f2tf32(float f) {
    uint32_t u;
    asm("cvt.rna.tf32.f32 %0, %1;" : "=r"(u) : "f"(f));
    return u;
}
__device__ __forceinline__ float ex2(float x) {
    float r;
    asm("ex2.approx.ftz.f32 %0, %1;" : "=f"(r) : "f"(x));
    return r;
}
__device__ __forceinline__ void mma_tf32(float* c, const uint32_t* a,
                                         const uint32_t* b) {
    asm volatile(
        "mma.sync.aligned.m16n8k8.row.col.f32.tf32.tf32.f32 "
        "{%0,%1,%2,%3}, {%4,%5,%6,%7}, {%8,%9}, {%0,%1,%2,%3};"
        : "+f"(c[0]), "+f"(c[1]), "+f"(c[2]), "+f"(c[3])
        : "r"(a[0]), "r"(a[1]), "r"(a[2]), "r"(a[3]), "r"(b[0]), "r"(b[1]));
}
__device__ __forceinline__ void cp_async16(uint32_t dst, const void* src) {
    asm volatile("cp.async.cg.shared.global [%0], [%1], 16;"
                 :: "r"(dst), "l"(src) : "memory");
}

// ===========================================================================
// conv_a: A[M,768] float -> A-fragment-native tf32 blocks.
// ===========================================================================
__global__ __launch_bounds__(256)
void conv_a(const float* __restrict__ A, uint32_t* __restrict__ out)
{
    const int rb = blockIdx.x;
    const float* Ab = A + (size_t)rb * 128 * GK;
    uint32_t* o = out + (size_t)rb * NCHUNK * 4096;

    #pragma unroll
    for (int i = 0; i < 12; i++) {
        int idx = threadIdx.x + (blockIdx.y * 12 + i) * 256;   // 0..24575
        int row = idx / 192;
        int col = (idx % 192) * 4;
        int chunk = col >> 5, c0 = col & 31;
        float4 v = *(const float4*)(Ab + (size_t)row * GK + col);
        int kt = c0 >> 3, c8hi = (c0 & 4) >> 2;
        int r8 = row & 15, mt = row >> 4;
        uint32_t tb  = (uint32_t)((kt * 8 + mt) << 9);
        uint32_t sw  = (uint32_t)((kt << 5) ^ ((r8 & 2) << 3));
        uint32_t reg = (uint32_t)((r8 >> 3) + 2 * c8hi);
        float vv[4] = {v.x, v.y, v.z, v.w};
        uint32_t* oc = o + chunk * 4096;
        #pragma unroll
        for (int j = 0; j < 4; j++) {
            uint32_t ln  = (uint32_t)((r8 & 7) * 4 + j);
            uint32_t off = (tb + (ln << 4) + (reg << 2)) ^ sw;
            oc[off >> 2] = f2tf32(vv[j]);
        }
    }
}

// ===========================================================================
// conv_b: W[768,N] float -> B-fragment-native tf32 blocks.
// ===========================================================================
__global__ __launch_bounds__(256)
void conv_b(const float* __restrict__ W, uint32_t* __restrict__ out, int N)
{
    const int cb = blockIdx.x;
    const int bn = cb * 128;
    uint32_t* o = out + (size_t)cb * NCHUNK * 4096;

    #pragma unroll
    for (int i = 0; i < 12; i++) {
        int idx = threadIdx.x + (blockIdx.y * 12 + i) * 256;   // 0..24575
        int k  = idx >> 5;              // 0..767
        int n0 = (idx & 31) << 2;       // 0..124
        float4 v = *(const float4*)(W + (size_t)k * N + bn + n0);
        int chunk = k >> 5, kl = k & 31;
        int kt = kl >> 3, k8 = kl & 7;
        uint32_t reg = (uint32_t)(k8 >> 2);
        uint32_t k3  = (uint32_t)(k8 & 3);
        float vv[4] = {v.x, v.y, v.z, v.w};
        uint32_t* oc = o + chunk * 4096;
        #pragma unroll
        for (int j = 0; j < 4; j++) {
            int n = n0 + j, nt = n >> 3, n8 = n & 7;
            uint32_t off = (uint32_t)(((kt * 16 + nt) << 8)
                         + ((n8 * 4 + (int)k3) << 3) + (reg << 2));
            off ^= (uint32_t)(nt << 3);
            oc[off >> 2] = f2tf32(vv[j]);
        }
    }
}

// ===========================================================================
// gemm2: pre-converted-operand tf32 GEMM.
// 3-stage cp.async pipeline, ONE __syncthreads per chunk.
// smem: 3 stages x (A 16KB | B 16KB) = 96 KB; 2 CTAs/SM.
// ===========================================================================
__global__ __launch_bounds__(256, 2)
void gemm2(const uint32_t* __restrict__ Af, const uint32_t* __restrict__ Bf,
           const float* __restrict__ bias, float* __restrict__ C, int N)
{
    extern __shared__ uint32_t sm2[];
    const uint32_t sbase = smem_u32(sm2);
    const int tid  = threadIdx.x;
    const int lane = tid & 31, wid = tid >> 5;
    const int wm   = wid >> 2, wn = wid & 3;
    const int bm   = blockIdx.y * 128, bn = blockIdx.x * 128;

    const uint4* Ab = (const uint4*)(Af + (size_t)blockIdx.y * NCHUNK * 4096);
    const uint4* Bb = (const uint4*)(Bf + (size_t)blockIdx.x * NCHUNK * 4096);

    float acc[4][4][4];
    #pragma unroll
    for (int mi = 0; mi < 4; mi++)
        #pragma unroll
        for (int ni = 0; ni < 4; ni++)
            #pragma unroll
            for (int r = 0; r < 4; r++) acc[mi][ni][r] = 0.f;

    #define COPYC(c, s)                                                       \
        do {                                                                  \
            const uint32_t dA = sbase + (uint32_t)(s) * 32768u;               \
            const uint32_t dB = dA + 16384u;                                  \
            const uint4* sa = Ab + (c) * 1024;                                \
            const uint4* sbp = Bb + (c) * 1024;                               \
            _Pragma("unroll")                                                 \
            for (int i = 0; i < 4; i++) {                                     \
                int idx = tid + i * 256;                                      \
                cp_async16(dA + (uint32_t)idx * 16u, sa + idx);               \
                cp_async16(dB + (uint32_t)idx * 16u, sbp + idx);              \
            }                                                                 \
            asm volatile("cp.async.commit_group;" ::: "memory");              \
        } while (0)

    COPYC(0, 0);
    COPYC(1, 1);

    for (int c = 0; c < NCHUNK; c++) {
        if (c + 1 < NCHUNK) {
            asm volatile("cp.async.wait_group 1;" ::: "memory");   // chunk c done
        } else {
            asm volatile("cp.async.wait_group 0;" ::: "memory");
        }
        __syncthreads();   // single sync: also guards buffer (c+2)%3 reuse

        if (c + 2 < NCHUNK) COPYC(c + 2, (c + 2) % 3);

        const uint32_t sA = sbase + (uint32_t)(c % 3) * 32768u;
        const uint32_t sB = sA + 16384u;
        #pragma unroll
        for (int ks = 0; ks < 4; ks++) {
            uint32_t af[4][4], bf[4][2];
            #pragma unroll
            for (int mi = 0; mi < 4; mi++) {
                uint32_t off = (uint32_t)(((ks * 8 + wm * 4 + mi) << 9)
                             + (lane << 4));
                off ^= (uint32_t)((ks << 5) ^ ((lane & 8) << 1));
                asm volatile("ld.shared.v4.b32 {%0,%1,%2,%3}, [%4];"
                             : "=r"(af[mi][0]), "=r"(af[mi][1]),
                               "=r"(af[mi][2]), "=r"(af[mi][3])
                             : "r"(sA + off));
            }
            #pragma unroll
            for (int ni = 0; ni < 4; ni++) {
                int bnt = wn * 4 + ni;
                uint32_t off = (uint32_t)(((ks * 16 + bnt) << 8) + (lane << 3));
                off ^= (uint32_t)(bnt << 3);
                asm volatile("ld.shared.v2.b32 {%0,%1}, [%2];"
                             : "=r"(bf[ni][0]), "=r"(bf[ni][1])
                             : "r"(sB + off));
            }
            #pragma unroll
            for (int mi = 0; mi < 4; mi++)
                #pragma unroll
                for (int ni = 0; ni < 4; ni++)
                    mma_tf32(acc[mi][ni], af[mi], bf[ni]);
        }
    }

    #pragma unroll
    for (int mi = 0; mi < 4; mi++) {
        int row = bm + wm * 64 + mi * 16 + (lane >> 2);
        #pragma unroll
        for (int ni = 0; ni < 4; ni++) {
            int col = bn + wn * 32 + ni * 8 + (lane & 3) * 2;
            float2 bb = *(const float2*)&bias[col];
            float2 o0, o1;
            o0.x = acc[mi][ni][0] + bb.x;
            o0.y = acc[mi][ni][1] + bb.y;
            o1.x = acc[mi][ni][2] + bb.x;
            o1.y = acc[mi][ni][3] + bb.y;
            *(float2*)&C[(size_t)row * N + col]       = o0;
            *(float2*)&C[(size_t)(row + 8) * N + col] = o1;
        }
    }
    #undef COPYC
}

// ===========================================================================
// K/V -> fragment-native tf32 conversion, once per (b,h,kv-tile).
// ===========================================================================
__global__ __launch_bounds__(128)
void conv_kv()
{
    const int tid = threadIdx.x;
    const int bh  = blockIdx.y;
    const int kt  = blockIdx.x;
    const int b   = bh / NHEADS;
    const int h   = bh % NHEADS;

    const float* base = g_qkv + (size_t)b * SEQ * QKVN + h * HD;
    uint32_t* out = g_kvf + ((size_t)bh * 16 + kt) * 8192;

    {
        const int krr = tid >> 4, kd0 = (tid & 15) * 4;
        const float* Kg = base + DIM + (size_t)(kt * 64) * QKVN;
        float4 t[8];
        #pragma unroll
        for (int p = 0; p < 8; p++)
            t[p] = *(const float4*)(Kg + (size_t)(p * 8 + krr) * QKVN + kd0);
        #pragma unroll
        for (int p = 0; p < 8; p++) {
            int r = p * 8 + krr;
            float v[4] = {t[p].x, t[p].y, t[p].z, t[p].w};
            #pragma unroll
            for (int e = 0; e < 4; e++) {
                int d = kd0 + e;
                uint32_t ln   = (uint32_t)(((r & 7) << 2) | (d & 3));
                uint32_t word = (uint32_t)(((r >> 3) * 8 + (d >> 3)) << 6)
                              + ((ln * 2u + (uint32_t)((d >> 2) & 1))
                                 ^ (uint32_t)((d >> 3) << 2));
                out[word] = f2tf32(v[e]);
            }
        }
    }
    {
        const int vrr = tid & 31, vd0 = (tid >> 5) * 4;
        const float* Vg = base + 2 * DIM + (size_t)(kt * 64) * QKVN;
        float4 t[8];
        #pragma unroll
        for (int p = 0; p < 8; p++) {
            int r  = (p & 1) * 32 + vrr;
            int d0 = (p >> 1) * 16 + vd0;
            t[p] = *(const float4*)(Vg + (size_t)r * QKVN + d0);
        }
        #pragma unroll
        for (int p = 0; p < 8; p++) {
            int r  = (p & 1) * 32 + vrr;
            int d0 = (p >> 1) * 16 + vd0;
            float v[4] = {t[p].x, t[p].y, t[p].z, t[p].w};
            #pragma unroll
            for (int e = 0; e < 4; e++) {
                int d = d0 + e;
                uint32_t ln   = (uint32_t)(((d & 7) << 2) | (r & 3));
                uint32_t word = (uint32_t)(((d >> 3) * 8 + (r >> 3)) << 6)
                              + ((ln * 2u + (uint32_t)((r >> 2) & 1))
                                 ^ (uint32_t)((r >> 3) << 2));
                out[4096 + word] = f2tf32(v[e]);
            }
        }
    }
}

// ===========================================================================
// Tensor-core flash attention: K double-buffered (2x16K) + V single (16K)
// + Ps (16K) = 64 KB -> 3 CTAs/SM (12 warps).
// Per iter: [wait K(kt)][sync][issue V(kt), K(kt+1)][S][wait V][sync][sm+PV]
// ===========================================================================
__global__ __launch_bounds__(128, 3)
void attn_mma()
{
    extern __shared__ uint32_t smu[];
    const uint32_t sb  = smem_u32(smu);
    const uint32_t VsB = sb + 32768u;
    const uint32_t PsB = sb + 49152u;

    const int tid  = threadIdx.x;
    const int lane = tid & 31, w = tid >> 5;
    const int bh   = blockIdx.y;
    const int b    = bh / NHEADS;
    const int h    = bh % NHEADS;
    const int q0   = blockIdx.x * 64;

    const float* base = g_qkv + (size_t)b * SEQ * QKVN + h * HD;

    const int r0w = w * 16 + (lane >> 2);
    const int c0  = lane & 3;
    uint32_t qa[8][4];
    {
        const float* Qp0 = base + (size_t)(q0 + r0w) * QKVN;
        const float* Qp1 = Qp0 + 8 * QKVN;
        #pragma unroll
        for (int ks = 0; ks < 8; ks++) {
            qa[ks][0] = f2tf32(Qp0[ks * 8 + c0]     * SC2);
            qa[ks][1] = f2tf32(Qp1[ks * 8 + c0]     * SC2);
            qa[ks][2] = f2tf32(Qp0[ks * 8 + c0 + 4] * SC2);
            qa[ks][3] = f2tf32(Qp1[ks * 8 + c0 + 4] * SC2);
        }
    }

    float oacc[8][4];
    #pragma unroll
    for (int nt = 0; nt < 8; nt++)
        #pragma unroll
        for (int r = 0; r < 4; r++) oacc[nt][r] = 0.f;
    float m0 = -INFINITY, m1 = -INFINITY, l0 = 0.f, l1 = 0.f;

    const int cc0 = 2 * c0, cc1 = cc0 + 1;
    const uint32_t pos0 = (uint32_t)((cc0 & 3) * 2 + (cc0 >> 2));
    const uint32_t pos1 = (uint32_t)((cc1 & 3) * 2 + (cc1 >> 2));
    const uint32_t swz  = (uint32_t)((r0w & 3) << 3);
    const uint32_t prow0 = PsB + (uint32_t)r0w * 256u;
    const uint32_t prow1 = prow0 + 8u * 256u;

    const uint4* kvsrc = (const uint4*)(g_kvf + (size_t)bh * 16 * 8192);

    // prologue: K(0) into K-buf 0
    {
        #pragma unroll
        for (int i = 0; i < 8; i++) {
            int idx = i * 128 + tid;
            cp_async16(sb + (uint32_t)idx * 16u, kvsrc + idx);
        }
        asm volatile("cp.async.commit_group;" ::: "memory");
    }

    for (int kt = 0; kt < SEQ / 64; kt++) {
        asm volatile("cp.async.wait_group 0;" ::: "memory");   // K(kt) landed
        __syncthreads();   // K(kt) visible; all warps done with V(kt-1), K(kt-1)

        // issue V(kt)
        {
            const uint4* src = kvsrc + (size_t)kt * 2048 + 1024;
            #pragma unroll
            for (int i = 0; i < 8; i++) {
                int idx = i * 128 + tid;
                cp_async16(VsB + (uint32_t)idx * 16u, src + idx);
            }
            asm volatile("cp.async.commit_group;" ::: "memory");
        }
        // issue K(kt+1)
        if (kt + 1 < SEQ / 64) {
            const uint4* src = kvsrc + (size_t)(kt + 1) * 2048;
            const uint32_t dst = sb + (uint32_t)((kt + 1) & 1) * 16384u;
            #pragma unroll
            for (int i = 0; i < 8; i++) {
                int idx = i * 128 + tid;
                cp_async16(dst + (uint32_t)idx * 16u, src + idx);
            }
            asm volatile("cp.async.commit_group;" ::: "memory");
        }

        const uint32_t KsB = sb + (uint32_t)(kt & 1) * 16384u;

        // ---- S = Q K^T (overlaps the V copy) ----
        float sacc[8][4];
        #pragma unroll
        for (int nt = 0; nt < 8; nt++)
            #pragma unroll
            for (int r = 0; r < 4; r++) sacc[nt][r] = 0.f;

        #pragma unroll
        for (int ks = 0; ks < 8; ks++) {
            uint32_t bf[8][2];
            #pragma unroll
            for (int nt = 0; nt < 8; nt++) {
                uint32_t off = (uint32_t)((nt * 8 + ks) << 6)
                             + (((uint32_t)lane * 2u) ^ (uint32_t)(ks << 2));
                asm volatile("ld.shared.v2.b32 {%0,%1}, [%2];"
                             : "=r"(bf[nt][0]), "=r"(bf[nt][1])
                             : "r"(KsB + off * 4u));
            }
            #pragma unroll
            for (int nt = 0; nt < 8; nt++)
                mma_tf32(sacc[nt], qa[ks], bf[nt]);
        }

        // V(kt) done (K(kt+1) may still be in flight)
        if (kt + 1 < SEQ / 64) {
            asm volatile("cp.async.wait_group 1;" ::: "memory");
        } else {
            asm volatile("cp.async.wait_group 0;" ::: "memory");
        }
        __syncthreads();

        // ---- online softmax (exp2 domain) ----
        float mx0 = -INFINITY, mx1 = -INFINITY;
        #pragma unroll
        for (int nt = 0; nt < 8; nt++) {
            mx0 = fmaxf(mx0, fmaxf(sacc[nt][0], sacc[nt][1]));
            mx1 = fmaxf(mx1, fmaxf(sacc[nt][2], sacc[nt][3]));
        }
        mx0 = fmaxf(mx0, __shfl_xor_sync(0xffffffffu, mx0, 1));
        mx0 = fmaxf(mx0, __shfl_xor_sync(0xffffffffu, mx0, 2));
        mx1 = fmaxf(mx1, __shfl_xor_sync(0xffffffffu, mx1, 1));
        mx1 = fmaxf(mx1, __shfl_xor_sync(0xffffffffu, mx1, 2));
        float mn0 = fmaxf(m0, mx0), mn1 = fmaxf(m1, mx1);
        float a0 = ex2(m0 - mn0), a1 = ex2(m1 - mn1);
        m0 = mn0; m1 = mn1;
        l0 *= a0;  l1 *= a1;

        float sum0 = 0.f, sum1 = 0.f;
        #pragma unroll
        for (int nt = 0; nt < 8; nt++) {
            float p00 = ex2(sacc[nt][0] - m0);
            float p01 = ex2(sacc[nt][1] - m0);
            float p10 = ex2(sacc[nt][2] - m1);
            float p11 = ex2(sacc[nt][3] - m1);
            sum0 += p00 + p01;
            sum1 += p10 + p11;
            oacc[nt][0] *= a0; oacc[nt][1] *= a0;
            oacc[nt][2] *= a1; oacc[nt][3] *= a1;
            uint32_t nb = (uint32_t)(nt * 8);
            asm volatile("st.shared.b32 [%0], %1;"
                         :: "r"(prow0 + ((nb + pos0) ^ swz) * 4u),
                            "r"(f2tf32(p00)) : "memory");
            asm volatile("st.shared.b32 [%0], %1;"
                         :: "r"(prow0 + ((nb + pos1) ^ swz) * 4u),
                            "r"(f2tf32(p01)) : "memory");
            asm volatile("st.shared.b32 [%0], %1;"
                         :: "r"(prow1 + ((nb + pos0) ^ swz) * 4u),
                            "r"(f2tf32(p10)) : "memory");
            asm volatile("st.shared.b32 [%0], %1;"
                         :: "r"(prow1 + ((nb + pos1) ^ swz) * 4u),
                            "r"(f2tf32(p11)) : "memory");
        }
        sum0 += __shfl_xor_sync(0xffffffffu, sum0, 1);
        sum0 += __shfl_xor_sync(0xffffffffu, sum0, 2);
        sum1 += __shfl_xor_sync(0xffffffffu, sum1, 1);
        sum1 += __shfl_xor_sync(0xffffffffu, sum1, 2);
        l0 += sum0; l1 += sum1;

        // ---- O += P V ----
        #pragma unroll
        for (int ks = 0; ks < 8; ks++) {
            uint32_t pa[4];
            uint32_t wo = (((uint32_t)(ks * 8 + c0 * 2)) ^ swz) * 4u;
            asm volatile("ld.shared.v2.b32 {%0,%1}, [%2];"
                         : "=r"(pa[0]), "=r"(pa[2]) : "r"(prow0 + wo));
            asm volatile("ld.shared.v2.b32 {%0,%1}, [%2];"
                         : "=r"(pa[1]), "=r"(pa[3]) : "r"(prow1 + wo));
            #pragma unroll
            for (int nt = 0; nt < 8; nt++) {
                uint32_t vb[2];
                uint32_t off = (uint32_t)((nt * 8 + ks) << 6)
                             + (((uint32_t)lane * 2u) ^ (uint32_t)(ks << 2));
                asm volatile("ld.shared.v2.b32 {%0,%1}, [%2];"
                             : "=r"(vb[0]), "=r"(vb[1]) : "r"(VsB + off * 4u));
                mma_tf32(oacc[nt], pa, vb);
            }
        }
    }

    {
        float inv0 = 1.f / l0, inv1 = 1.f / l1;
        float* O0 = g_att + (size_t)(b * SEQ + q0 + r0w) * DIM + h * HD;
        float* O1 = O0 + 8 * DIM;
        #pragma unroll
        for (int nt = 0; nt < 8; nt++) {
            int col = nt * 8 + cc0;
            float2 v0 = {oacc[nt][0] * inv0, oacc[nt][1] * inv0};
            float2 v1 = {oacc[nt][2] * inv1, oacc[nt][3] * inv1};
            *(float2*)(O0 + col) = v0;
            *(float2*)(O1 + col) = v1;
        }
    }
}

// ---------------------------------------------------------------------------
extern "C" void kernel_launch(void* const* d_in, const int* in_sizes, int n_in,
                              void* d_out, int out_size)
{
    const float* x      = (const float*)d_in[0];
    const float* w_qkv  = (const float*)d_in[1];
    const float* b_qkv  = (const float*)d_in[2];
    const float* w_proj = (const float*)d_in[3];
    const float* b_proj = (const float*)d_in[4];
    float* out = (float*)d_out;

    float *qkv = nullptr, *att = nullptr;
    uint32_t *xf = nullptr, *af2 = nullptr, *wqf = nullptr, *wpf = nullptr;
    cudaGetSymbolAddress((void**)&qkv, g_qkv);
    cudaGetSymbolAddress((void**)&att, g_att);
    cudaGetSymbolAddress((void**)&xf,  g_xf);
    cudaGetSymbolAddress((void**)&af2, g_af2);
    cudaGetSymbolAddress((void**)&wqf, g_wqf);
    cudaGetSymbolAddress((void**)&wpf, g_wpf);

    const int gemm_smem = 98304;   // 3 stages x 32 KB
    const int attn_smem = 65536;   // K0|K1|V|Ps = 4 x 16 KB
    cudaFuncSetAttribute(gemm2,
                         cudaFuncAttributeMaxDynamicSharedMemorySize, gemm_smem);
    cudaFuncSetAttribute(attn_mma,
                         cudaFuncAttributeMaxDynamicSharedMemorySize, attn_smem);

    // 0) operand conversions (x, weights)
    conv_a<<<dim3(64, 8), 256>>>(x, xf);
    conv_b<<<dim3(18, 8), 256>>>(w_qkv, wqf, QKVN);
    conv_b<<<dim3(6, 8),  256>>>(w_proj, wpf, DIM);

    // 1) QKV projection
    gemm2<<<dim3(QKVN / 128, MROWS / 128), 256, gemm_smem>>>(
        xf, wqf, b_qkv, qkv, QKVN);

    // 2) attention
    conv_kv<<<dim3(16, BATCH * NHEADS), 128>>>();
    attn_mma<<<dim3(SEQ / 64, BATCH * NHEADS), 128, attn_smem>>>();

    // 3) output projection
    conv_a<<<dim3(64, 8), 256>>>(att, af2);
    gemm2<<<dim3(DIM / 128, MROWS / 128), 256, gemm_smem>>>(
        af2, wpf, b_proj, out, DIM);
}

// round 11
// speedup vs baseline: 2.5667x; 1.8553x over previous
#include <cuda_runtime.h>
#include <math.h>
#include <stdint.h>

#define DIM     768
#define NHEADS  12
#define HD      64
#define BATCH   8
#define SEQ     1024
#define MROWS   (BATCH*SEQ)     /* 8192 */
#define QKVN    (3*DIM)         /* 2304 */
#define SC2     0.1803368801111244f   /* 64^-0.5 * log2(e) */
#define GK      768
#define NCHUNK  24

// Scratch (allocation-free rule: __device__ globals)
__device__ __align__(1024) float    g_qkv[(size_t)MROWS * QKVN];  // [B*N, 3*DIM]
__device__ __align__(1024) float    g_att[(size_t)MROWS * DIM];   // [B*N, DIM]
__device__ __align__(1024) uint32_t g_kvf[(size_t)BATCH * NHEADS * 16 * 4096];
// fp16 fragment-native operand scratch (words = f16x2):
__device__ __align__(1024) uint32_t g_xf [(size_t)64 * NCHUNK * 2048];  // x    A-frags
__device__ __align__(1024) uint32_t g_af2[(size_t)64 * NCHUNK * 2048];  // att  A-frags
__device__ __align__(1024) uint32_t g_wqf[(size_t)18 * NCHUNK * 2048];  // Wqkv B-frags
__device__ __align__(1024) uint32_t g_wpf[(size_t) 6 * NCHUNK * 2048];  // Wprj B-frags

__device__ __forceinline__ uint32_t smem_u32(const void* p) {
    uint32_t a;
    asm("{ .reg .u64 t; cvta.to.shared.u64 t, %1; cvt.u32.u64 %0, t; }"
        : "=r"(a) : "l"(p));
    return a;
}
// pack two f32 -> f16x2 (first source -> upper half)
__device__ __forceinline__ uint32_t pack_h2(float hi, float lo) {
    uint32_t r;
    asm("cvt.rn.f16x2.f32 %0, %1, %2;" : "=r"(r) : "f"(hi), "f"(lo));
    return r;
}
__device__ __forceinline__ float ex2(float x) {
    float r;
    asm("ex2.approx.ftz.f32 %0, %1;" : "=f"(r) : "f"(x));
    return r;
}
__device__ __forceinline__ void mma_f16(float* c, const uint32_t* a,
                                        const uint32_t* b) {
    asm volatile(
        "mma.sync.aligned.m16n8k16.row.col.f32.f16.f16.f32 "
        "{%0,%1,%2,%3}, {%4,%5,%6,%7}, {%8,%9}, {%0,%1,%2,%3};"
        : "+f"(c[0]), "+f"(c[1]), "+f"(c[2]), "+f"(c[3])
        : "r"(a[0]), "r"(a[1]), "r"(a[2]), "r"(a[3]), "r"(b[0]), "r"(b[1]));
}
__device__ __forceinline__ void cp_async16(uint32_t dst, const void* src) {
    asm volatile("cp.async.cg.shared.global [%0], [%1], 16;"
                 :: "r"(dst), "l"(src) : "memory");
}

// ===========================================================================
// conv_a: A[M,768] f32 -> fp16 A-fragment blocks.
// word = (rb*24+chunk)*2048 + (k16s*8 + mt)*128 + lane*4 + reg
// lane=(row&7)*4+((klo&7)>>1); reg=(klo>=8)*2+((row&15)>=8)
// ===========================================================================
__global__ __launch_bounds__(256)
void conv_a(const float* __restrict__ A, uint32_t* __restrict__ out)
{
    const int rb = blockIdx.x;
    const float* Ab = A + (size_t)rb * 128 * GK;
    uint32_t* o = out + (size_t)rb * NCHUNK * 2048;

    #pragma unroll
    for (int i = 0; i < 12; i++) {
        int idx = threadIdx.x + (blockIdx.y * 12 + i) * 256;   // 0..24575
        int row = idx / 192;
        int col = (idx % 192) * 4;
        int chunk = col >> 5, c0 = col & 31;
        float4 v = *(const float4*)(Ab + (size_t)row * GK + col);
        int k16s = c0 >> 4, klo = c0 & 15;           // klo in {0,4,8,12}
        int mt = row >> 4;
        uint32_t reg  = (uint32_t)(((klo >= 8) ? 2 : 0) + (((row & 15) >= 8) ? 1 : 0));
        uint32_t lane = (uint32_t)((row & 7) * 4 + ((klo & 7) >> 1));
        uint32_t* oc = o + (size_t)chunk * 2048 + (k16s * 8 + mt) * 128;
        oc[lane * 4 + reg]       = pack_h2(v.y, v.x);
        oc[(lane + 1) * 4 + reg] = pack_h2(v.w, v.z);
    }
}

// ===========================================================================
// conv_b: W[768,N] f32 -> fp16 B-fragment blocks.
// word = (cb*24+chunk)*2048 + (k16s*16 + nt)*64 + lane*2 + reg
// lane=(n&7)*4+((klo&7)>>1); reg=(klo&15)>=8
// ===========================================================================
__global__ __launch_bounds__(256)
void conv_b(const float* __restrict__ W, uint32_t* __restrict__ out, int N)
{
    const int cb = blockIdx.x;
    const int bn = cb * 128;
    uint32_t* o = out + (size_t)cb * NCHUNK * 2048;

    #pragma unroll
    for (int i = 0; i < 12; i++) {
        int idx = threadIdx.x + (blockIdx.y * 12 + i) * 256;   // 0..24575
        int n  = idx & 127;
        int k0 = (idx >> 7) * 4;        // 0..764 step 4
        const float* p = W + (size_t)k0 * N + bn + n;
        float v0 = p[0], v1 = p[N], v2 = p[2 * (size_t)N], v3 = p[3 * (size_t)N];
        int chunk = k0 >> 5, kl0 = k0 & 31;
        int k16s = kl0 >> 4, klo = kl0 & 15;         // klo in {0,4,8,12}
        int nt = n >> 3, n8 = n & 7;
        uint32_t reg  = (klo >= 8) ? 1u : 0u;
        uint32_t lane = (uint32_t)(n8 * 4 + ((klo & 7) >> 1));
        uint32_t* oc = o + (size_t)chunk * 2048 + (k16s * 16 + nt) * 64;
        oc[lane * 2 + reg]       = pack_h2(v1, v0);
        oc[(lane + 1) * 2 + reg] = pack_h2(v3, v2);
    }
}

// ===========================================================================
// gemm2: fp16 m16n8k16 GEMM, pre-converted operands.
// 3-stage cp.async pipeline (16 KB/stage: A 8K | B 8K), one sync/chunk.
// ===========================================================================
__global__ __launch_bounds__(256, 2)
void gemm2(const uint32_t* __restrict__ Af, const uint32_t* __restrict__ Bf,
           const float* __restrict__ bias, float* __restrict__ C, int N)
{
    extern __shared__ uint32_t sm2[];
    const uint32_t sbase = smem_u32(sm2);
    const int tid  = threadIdx.x;
    const int lane = tid & 31, wid = tid >> 5;
    const int wm   = wid >> 2, wn = wid & 3;
    const int bm   = blockIdx.y * 128, bn = blockIdx.x * 128;

    const uint4* Ab = (const uint4*)(Af + (size_t)blockIdx.y * NCHUNK * 2048);
    const uint4* Bb = (const uint4*)(Bf + (size_t)blockIdx.x * NCHUNK * 2048);

    float acc[4][4][4];
    #pragma unroll
    for (int mi = 0; mi < 4; mi++)
        #pragma unroll
        for (int ni = 0; ni < 4; ni++)
            #pragma unroll
            for (int r = 0; r < 4; r++) acc[mi][ni][r] = 0.f;

    #define COPYC(c, s)                                                       \
        do {                                                                  \
            const uint32_t dA = sbase + (uint32_t)(s) * 16384u;               \
            const uint32_t dB = dA + 8192u;                                   \
            const uint4* sa  = Ab + (c) * 512;                                \
            const uint4* sbp = Bb + (c) * 512;                                \
            _Pragma("unroll")                                                 \
            for (int i = 0; i < 2; i++) {                                     \
                int idx = tid + i * 256;                                      \
                cp_async16(dA + (uint32_t)idx * 16u, sa + idx);               \
                cp_async16(dB + (uint32_t)idx * 16u, sbp + idx);              \
            }                                                                 \
            asm volatile("cp.async.commit_group;" ::: "memory");              \
        } while (0)

    COPYC(0, 0);
    COPYC(1, 1);

    for (int c = 0; c < NCHUNK; c++) {
        if (c + 1 < NCHUNK) {
            asm volatile("cp.async.wait_group 1;" ::: "memory");
        } else {
            asm volatile("cp.async.wait_group 0;" ::: "memory");
        }
        __syncthreads();

        if (c + 2 < NCHUNK) COPYC(c + 2, (c + 2) % 3);

        const uint32_t sA = sbase + (uint32_t)(c % 3) * 16384u;
        const uint32_t sB = sA + 8192u;
        #pragma unroll
        for (int ks = 0; ks < 2; ks++) {
            uint32_t af[4][4], bf[4][2];
            #pragma unroll
            for (int mi = 0; mi < 4; mi++) {
                uint32_t off = (uint32_t)(((ks * 8 + wm * 4 + mi) << 9)
                             + (lane << 4));
                asm volatile("ld.shared.v4.b32 {%0,%1,%2,%3}, [%4];"
                             : "=r"(af[mi][0]), "=r"(af[mi][1]),
                               "=r"(af[mi][2]), "=r"(af[mi][3])
                             : "r"(sA + off));
            }
            #pragma unroll
            for (int ni = 0; ni < 4; ni++) {
                uint32_t off = (uint32_t)(((ks * 16 + wn * 4 + ni) << 8)
                             + (lane << 3));
                asm volatile("ld.shared.v2.b32 {%0,%1}, [%2];"
                             : "=r"(bf[ni][0]), "=r"(bf[ni][1])
                             : "r"(sB + off));
            }
            #pragma unroll
            for (int mi = 0; mi < 4; mi++)
                #pragma unroll
                for (int ni = 0; ni < 4; ni++)
                    mma_f16(acc[mi][ni], af[mi], bf[ni]);
        }
    }

    #pragma unroll
    for (int mi = 0; mi < 4; mi++) {
        int row = bm + wm * 64 + mi * 16 + (lane >> 2);
        #pragma unroll
        for (int ni = 0; ni < 4; ni++) {
            int col = bn + wn * 32 + ni * 8 + (lane & 3) * 2;
            float2 bb = *(const float2*)&bias[col];
            float2 o0, o1;
            o0.x = acc[mi][ni][0] + bb.x;
            o0.y = acc[mi][ni][1] + bb.y;
            o1.x = acc[mi][ni][2] + bb.x;
            o1.y = acc[mi][ni][3] + bb.y;
            *(float2*)&C[(size_t)row * N + col]       = o0;
            *(float2*)&C[(size_t)(row + 8) * N + col] = o1;
        }
    }
    #undef COPYC
}

// ===========================================================================
// conv_kv: K/V -> fp16 fragment blocks, once per (b,h,kv-tile).
// per tile: K 2048 words | V^T 2048 words (16 KB total).
// K  word: (nt*4 + k16s)*64 + lane*2 + reg  (n=kv row, k=hd)
// V^T word: same formula with n=hd, k=kv.
// ===========================================================================
__global__ __launch_bounds__(128)
void conv_kv()
{
    const int tid = threadIdx.x;
    const int bh  = blockIdx.y;
    const int kt  = blockIdx.x;
    const int b   = bh / NHEADS;
    const int h   = bh % NHEADS;

    const float* base = g_qkv + (size_t)b * SEQ * QKVN + h * HD;
    uint32_t* out  = g_kvf + ((size_t)bh * 16 + kt) * 4096;
    uint32_t* outV = out + 2048;

    // ---- K tile ----
    {
        const int krr = tid >> 4, kd0 = (tid & 15) * 4;   // kd0 in {0,4,...,60}
        const float* Kg = base + DIM + (size_t)(kt * 64) * QKVN;
        #pragma unroll
        for (int p = 0; p < 8; p++) {
            int r = p * 8 + krr;
            float4 v = *(const float4*)(Kg + (size_t)r * QKVN + kd0);
            int nt = r >> 3, k16s = kd0 >> 4, klo = kd0 & 15;
            uint32_t reg  = (klo >= 8) ? 1u : 0u;
            uint32_t lane = (uint32_t)((r & 7) * 4 + ((klo & 7) >> 1));
            uint32_t* oc = out + (nt * 4 + k16s) * 64;
            oc[lane * 2 + reg]       = pack_h2(v.y, v.x);
            oc[(lane + 1) * 2 + reg] = pack_h2(v.w, v.z);
        }
    }
    // ---- V^T tile (k = kv pairs -> strided row loads) ----
    {
        const float* Vg = base + 2 * DIM + (size_t)(kt * 64) * QKVN;
        #pragma unroll
        for (int p = 0; p < 8; p++) {
            int task = tid + p * 128;       // 0..1023
            int d  = task & 63;
            int r0 = (task >> 6) * 4;       // 0..60 step 4
            const float* vp = Vg + (size_t)r0 * QKVN + d;
            float v0 = vp[0], v1 = vp[QKVN], v2 = vp[2 * QKVN], v3 = vp[3 * QKVN];
            int nt = d >> 3, n8 = d & 7;
            int k16s = r0 >> 4, klo = r0 & 15;
            uint32_t reg  = (klo >= 8) ? 1u : 0u;
            uint32_t lane = (uint32_t)(n8 * 4 + ((klo & 7) >> 1));
            uint32_t* oc = outV + (nt * 4 + k16s) * 64;
            oc[lane * 2 + reg]       = pack_h2(v1, v0);
            oc[(lane + 1) * 2 + reg] = pack_h2(v3, v2);
        }
    }
}

// ===========================================================================
// fp16 tensor-core flash attention. CTA = (b,h,64q), 128 threads.
// SMEM: K0 8K | K1 8K | V 8K | Ps 8K = 32 KB -> 4 CTAs/SM.
// Per iter: [wait K(kt)][sync][issue V(kt),K(kt+1)][S][wait V][sync][sm+PV]
// ===========================================================================
__global__ __launch_bounds__(128, 4)
void attn_mma()
{
    extern __shared__ uint32_t smu[];
    const uint32_t sb  = smem_u32(smu);
    const uint32_t VsB = sb + 16384u;
    const uint32_t PsB = sb + 24576u;

    const int tid  = threadIdx.x;
    const int lane = tid & 31, w = tid >> 5;
    const int bh   = blockIdx.y;
    const int b    = bh / NHEADS;
    const int h    = bh % NHEADS;
    const int q0   = blockIdx.x * 64;

    const float* base = g_qkv + (size_t)b * SEQ * QKVN + h * HD;

    const int r0w = w * 16 + (lane >> 2);
    const int c0  = lane & 3;
    const int cc0 = 2 * c0;

    // ---- Q as fp16 A-fragments (pre-scaled to exp2 domain) ----
    uint32_t qa[4][4];
    {
        const float* Qp0 = base + (size_t)(q0 + r0w) * QKVN;
        const float* Qp1 = Qp0 + 8 * QKVN;
        #pragma unroll
        for (int ks = 0; ks < 4; ks++) {
            float2 a0 = *(const float2*)(Qp0 + ks * 16 + cc0);
            float2 a1 = *(const float2*)(Qp1 + ks * 16 + cc0);
            float2 a2 = *(const float2*)(Qp0 + ks * 16 + 8 + cc0);
            float2 a3 = *(const float2*)(Qp1 + ks * 16 + 8 + cc0);
            qa[ks][0] = pack_h2(a0.y * SC2, a0.x * SC2);
            qa[ks][1] = pack_h2(a1.y * SC2, a1.x * SC2);
            qa[ks][2] = pack_h2(a2.y * SC2, a2.x * SC2);
            qa[ks][3] = pack_h2(a3.y * SC2, a3.x * SC2);
        }
    }

    float oacc[8][4];
    #pragma unroll
    for (int nt = 0; nt < 8; nt++)
        #pragma unroll
        for (int r = 0; r < 4; r++) oacc[nt][r] = 0.f;
    float m0 = -INFINITY, m1 = -INFINITY, l0 = 0.f, l1 = 0.f;

    const uint32_t Pwarp = PsB + (uint32_t)w * 2048u;

    const uint4* kvsrc = (const uint4*)(g_kvf + (size_t)bh * 16 * 4096);

    // prologue: K(0) into K-buf 0 (512 uint4)
    {
        #pragma unroll
        for (int i = 0; i < 4; i++) {
            int idx = i * 128 + tid;
            cp_async16(sb + (uint32_t)idx * 16u, kvsrc + idx);
        }
        asm volatile("cp.async.commit_group;" ::: "memory");
    }

    for (int kt = 0; kt < SEQ / 64; kt++) {
        asm volatile("cp.async.wait_group 0;" ::: "memory");   // K(kt) landed
        __syncthreads();

        // issue V(kt)
        {
            const uint4* src = kvsrc + (size_t)kt * 1024 + 512;
            #pragma unroll
            for (int i = 0; i < 4; i++) {
                int idx = i * 128 + tid;
                cp_async16(VsB + (uint32_t)idx * 16u, src + idx);
            }
            asm volatile("cp.async.commit_group;" ::: "memory");
        }
        // issue K(kt+1)
        if (kt + 1 < SEQ / 64) {
            const uint4* src = kvsrc + (size_t)(kt + 1) * 1024;
            const uint32_t dst = sb + (uint32_t)((kt + 1) & 1) * 8192u;
            #pragma unroll
            for (int i = 0; i < 4; i++) {
                int idx = i * 128 + tid;
                cp_async16(dst + (uint32_t)idx * 16u, src + idx);
            }
            asm volatile("cp.async.commit_group;" ::: "memory");
        }

        const uint32_t KsB = sb + (uint32_t)(kt & 1) * 8192u;

        // ---- S = Q K^T (overlaps V copy) ----
        float sacc[8][4];
        #pragma unroll
        for (int nt = 0; nt < 8; nt++)
            #pragma unroll
            for (int r = 0; r < 4; r++) sacc[nt][r] = 0.f;

        #pragma unroll
        for (int ks = 0; ks < 4; ks++) {
            uint32_t bf[8][2];
            #pragma unroll
            for (int nt = 0; nt < 8; nt++) {
                uint32_t off = (uint32_t)((nt * 4 + ks) << 8) + (lane << 3);
                asm volatile("ld.shared.v2.b32 {%0,%1}, [%2];"
                             : "=r"(bf[nt][0]), "=r"(bf[nt][1])
                             : "r"(KsB + off));
            }
            #pragma unroll
            for (int nt = 0; nt < 8; nt++)
                mma_f16(sacc[nt], qa[ks], bf[nt]);
        }

        if (kt + 1 < SEQ / 64) {
            asm volatile("cp.async.wait_group 1;" ::: "memory");   // V(kt) done
        } else {
            asm volatile("cp.async.wait_group 0;" ::: "memory");
        }
        __syncthreads();

        // ---- online softmax (exp2 domain) ----
        float mx0 = -INFINITY, mx1 = -INFINITY;
        #pragma unroll
        for (int nt = 0; nt < 8; nt++) {
            mx0 = fmaxf(mx0, fmaxf(sacc[nt][0], sacc[nt][1]));
            mx1 = fmaxf(mx1, fmaxf(sacc[nt][2], sacc[nt][3]));
        }
        mx0 = fmaxf(mx0, __shfl_xor_sync(0xffffffffu, mx0, 1));
        mx0 = fmaxf(mx0, __shfl_xor_sync(0xffffffffu, mx0, 2));
        mx1 = fmaxf(mx1, __shfl_xor_sync(0xffffffffu, mx1, 1));
        mx1 = fmaxf(mx1, __shfl_xor_sync(0xffffffffu, mx1, 2));
        float mn0 = fmaxf(m0, mx0), mn1 = fmaxf(m1, mx1);
        float a0 = ex2(m0 - mn0), a1 = ex2(m1 - mn1);
        m0 = mn0; m1 = mn1;
        l0 *= a0;  l1 *= a1;

        float sum0 = 0.f, sum1 = 0.f;
        #pragma unroll
        for (int nt = 0; nt < 8; nt++) {
            float p00 = ex2(sacc[nt][0] - m0);
            float p01 = ex2(sacc[nt][1] - m0);
            float p10 = ex2(sacc[nt][2] - m1);
            float p11 = ex2(sacc[nt][3] - m1);
            sum0 += p00 + p01;
            sum1 += p10 + p11;
            oacc[nt][0] *= a0; oacc[nt][1] *= a0;
            oacc[nt][2] *= a1; oacc[nt][3] *= a1;
            // P store: one f16x2 word per row-half (A-frag native)
            uint32_t baddr = Pwarp + (uint32_t)((nt >> 1) * 512)
                           + (uint32_t)(lane << 4) + (uint32_t)((nt & 1) * 8);
            asm volatile("st.shared.b32 [%0], %1;"
                         :: "r"(baddr),     "r"(pack_h2(p01, p00)) : "memory");
            asm volatile("st.shared.b32 [%0], %1;"
                         :: "r"(baddr + 4), "r"(pack_h2(p11, p10)) : "memory");
        }
        sum0 += __shfl_xor_sync(0xffffffffu, sum0, 1);
        sum0 += __shfl_xor_sync(0xffffffffu, sum0, 2);
        sum1 += __shfl_xor_sync(0xffffffffu, sum1, 1);
        sum1 += __shfl_xor_sync(0xffffffffu, sum1, 2);
        l0 += sum0; l1 += sum1;

        // ---- O += P V (P warp-private; no barrier) ----
        #pragma unroll
        for (int ks = 0; ks < 4; ks++) {
            uint32_t pa[4];
            asm volatile("ld.shared.v4.b32 {%0,%1,%2,%3}, [%4];"
                         : "=r"(pa[0]), "=r"(pa[1]), "=r"(pa[2]), "=r"(pa[3])
                         : "r"(Pwarp + (uint32_t)(ks * 512) + (uint32_t)(lane << 4)));
            #pragma unroll
            for (int nt = 0; nt < 8; nt++) {
                uint32_t vb[2];
                uint32_t off = (uint32_t)((nt * 4 + ks) << 8) + (lane << 3);
                asm volatile("ld.shared.v2.b32 {%0,%1}, [%2];"
                             : "=r"(vb[0]), "=r"(vb[1]) : "r"(VsB + off));
                mma_f16(oacc[nt], pa, vb);
            }
        }
    }

    // ---- normalize, write out ----
    {
        float inv0 = 1.f / l0, inv1 = 1.f / l1;
        float* O0 = g_att + (size_t)(b * SEQ + q0 + r0w) * DIM + h * HD;
        float* O1 = O0 + 8 * DIM;
        #pragma unroll
        for (int nt = 0; nt < 8; nt++) {
            int col = nt * 8 + cc0;
            float2 v0 = {oacc[nt][0] * inv0, oacc[nt][1] * inv0};
            float2 v1 = {oacc[nt][2] * inv1, oacc[nt][3] * inv1};
            *(float2*)(O0 + col) = v0;
            *(float2*)(O1 + col) = v1;
        }
    }
}

// ---------------------------------------------------------------------------
extern "C" void kernel_launch(void* const* d_in, const int* in_sizes, int n_in,
                              void* d_out, int out_size)
{
    const float* x      = (const float*)d_in[0];
    const float* w_qkv  = (const float*)d_in[1];
    const float* b_qkv  = (const float*)d_in[2];
    const float* w_proj = (const float*)d_in[3];
    const float* b_proj = (const float*)d_in[4];
    float* out = (float*)d_out;

    float *qkv = nullptr, *att = nullptr;
    uint32_t *xf = nullptr, *af2 = nullptr, *wqf = nullptr, *wpf = nullptr;
    cudaGetSymbolAddress((void**)&qkv, g_qkv);
    cudaGetSymbolAddress((void**)&att, g_att);
    cudaGetSymbolAddress((void**)&xf,  g_xf);
    cudaGetSymbolAddress((void**)&af2, g_af2);
    cudaGetSymbolAddress((void**)&wqf, g_wqf);
    cudaGetSymbolAddress((void**)&wpf, g_wpf);

    const int gemm_smem = 49152;   // 3 stages x 16 KB
    const int attn_smem = 32768;   // K0|K1|V|Ps = 4 x 8 KB
    cudaFuncSetAttribute(gemm2,
                         cudaFuncAttributeMaxDynamicSharedMemorySize, gemm_smem);
    cudaFuncSetAttribute(attn_mma,
                         cudaFuncAttributeMaxDynamicSharedMemorySize, attn_smem);

    // 0) operand conversions (x, weights) -> fp16 fragments
    conv_a<<<dim3(64, 8), 256>>>(x, xf);
    conv_b<<<dim3(18, 8), 256>>>(w_qkv, wqf, QKVN);
    conv_b<<<dim3(6, 8),  256>>>(w_proj, wpf, DIM);

    // 1) QKV projection (fp16 tensor cores)
    gemm2<<<dim3(QKVN / 128, MROWS / 128), 256, gemm_smem>>>(
        xf, wqf, b_qkv, qkv, QKVN);

    // 2) attention
    conv_kv<<<dim3(16, BATCH * NHEADS), 128>>>();
    attn_mma<<<dim3(SEQ / 64, BATCH * NHEADS), 128, attn_smem>>>();

    // 3) output projection
    conv_a<<<dim3(64, 8), 256>>>(att, af2);
    gemm2<<<dim3(DIM / 128, MROWS / 128), 256, gemm_smem>>>(
        af2, wpf, b_proj, out, DIM);
}

// round 12
// speedup vs baseline: 2.7178x; 1.0589x over previous
#include <cuda_runtime.h>
#include <math.h>
#include <stdint.h>

#define DIM     768
#define NHEADS  12
#define HD      64
#define BATCH   8
#define SEQ     1024
#define MROWS   (BATCH*SEQ)     /* 8192 */
#define QKVN    (3*DIM)         /* 2304 */
#define SC2     0.1803368801111244f   /* 64^-0.5 * log2(e) */
#define GK      768
#define NCHUNK  24

// Scratch (allocation-free rule: __device__ globals)
__device__ __align__(1024) float    g_qkv[(size_t)MROWS * QKVN];  // [B*N, 3*DIM]
__device__ __align__(1024) float    g_att[(size_t)MROWS * DIM];   // [B*N, DIM]
__device__ __align__(1024) uint32_t g_kvf[(size_t)BATCH * NHEADS * 16 * 4096];
// fp16 fragment-native operand scratch (words = f16x2):
__device__ __align__(1024) uint32_t g_xf [(size_t)64 * NCHUNK * 2048];  // x    A-frags
__device__ __align__(1024) uint32_t g_af2[(size_t)64 * NCHUNK * 2048];  // att  A-frags
__device__ __align__(1024) uint32_t g_wqf[(size_t)18 * NCHUNK * 2048];  // Wqkv B-frags
__device__ __align__(1024) uint32_t g_wpf[(size_t) 6 * NCHUNK * 2048];  // Wprj B-frags

__device__ __forceinline__ uint32_t smem_u32(const void* p) {
    uint32_t a;
    asm("{ .reg .u64 t; cvta.to.shared.u64 t, %1; cvt.u32.u64 %0, t; }"
        : "=r"(a) : "l"(p));
    return a;
}
// pack two f32 -> f16x2 (first source -> upper half)
__device__ __forceinline__ uint32_t pack_h2(float hi, float lo) {
    uint32_t r;
    asm("cvt.rn.f16x2.f32 %0, %1, %2;" : "=r"(r) : "f"(hi), "f"(lo));
    return r;
}
__device__ __forceinline__ float ex2(float x) {
    float r;
    asm("ex2.approx.ftz.f32 %0, %1;" : "=f"(r) : "f"(x));
    return r;
}
__device__ __forceinline__ void mma_f16(float* c, const uint32_t* a,
                                        const uint32_t* b) {
    asm volatile(
        "mma.sync.aligned.m16n8k16.row.col.f32.f16.f16.f32 "
        "{%0,%1,%2,%3}, {%4,%5,%6,%7}, {%8,%9}, {%0,%1,%2,%3};"
        : "+f"(c[0]), "+f"(c[1]), "+f"(c[2]), "+f"(c[3])
        : "r"(a[0]), "r"(a[1]), "r"(a[2]), "r"(a[3]), "r"(b[0]), "r"(b[1]));
}
__device__ __forceinline__ void cp_async16(uint32_t dst, const void* src) {
    asm volatile("cp.async.cg.shared.global [%0], [%1], 16;"
                 :: "r"(dst), "l"(src) : "memory");
}

// ===========================================================================
// conv_a: A[M,768] f32 -> fp16 A-fragment blocks.
// ===========================================================================
__global__ __launch_bounds__(256)
void conv_a(const float* __restrict__ A, uint32_t* __restrict__ out)
{
    const int rb = blockIdx.x;
    const float* Ab = A + (size_t)rb * 128 * GK;
    uint32_t* o = out + (size_t)rb * NCHUNK * 2048;

    #pragma unroll
    for (int i = 0; i < 12; i++) {
        int idx = threadIdx.x + (blockIdx.y * 12 + i) * 256;   // 0..24575
        int row = idx / 192;
        int col = (idx % 192) * 4;
        int chunk = col >> 5, c0 = col & 31;
        float4 v = *(const float4*)(Ab + (size_t)row * GK + col);
        int k16s = c0 >> 4, klo = c0 & 15;           // klo in {0,4,8,12}
        int mt = row >> 4;
        uint32_t reg  = (uint32_t)(((klo >= 8) ? 2 : 0) + (((row & 15) >= 8) ? 1 : 0));
        uint32_t lane = (uint32_t)((row & 7) * 4 + ((klo & 7) >> 1));
        uint32_t* oc = o + (size_t)chunk * 2048 + (k16s * 8 + mt) * 128;
        oc[lane * 4 + reg]       = pack_h2(v.y, v.x);
        oc[(lane + 1) * 4 + reg] = pack_h2(v.w, v.z);
    }
}

// ===========================================================================
// conv_b: W[768,N] f32 -> fp16 B-fragment blocks.
// ===========================================================================
__global__ __launch_bounds__(256)
void conv_b(const float* __restrict__ W, uint32_t* __restrict__ out, int N)
{
    const int cb = blockIdx.x;
    const int bn = cb * 128;
    uint32_t* o = out + (size_t)cb * NCHUNK * 2048;

    #pragma unroll
    for (int i = 0; i < 12; i++) {
        int idx = threadIdx.x + (blockIdx.y * 12 + i) * 256;   // 0..24575
        int n  = idx & 127;
        int k0 = (idx >> 7) * 4;        // 0..764 step 4
        const float* p = W + (size_t)k0 * N + bn + n;
        float v0 = p[0], v1 = p[N], v2 = p[2 * (size_t)N], v3 = p[3 * (size_t)N];
        int chunk = k0 >> 5, kl0 = k0 & 31;
        int k16s = kl0 >> 4, klo = kl0 & 15;         // klo in {0,4,8,12}
        int nt = n >> 3, n8 = n & 7;
        uint32_t reg  = (klo >= 8) ? 1u : 0u;
        uint32_t lane = (uint32_t)(n8 * 4 + ((klo & 7) >> 1));
        uint32_t* oc = o + (size_t)chunk * 2048 + (k16s * 16 + nt) * 64;
        oc[lane * 2 + reg]       = pack_h2(v1, v0);
        oc[(lane + 1) * 2 + reg] = pack_h2(v3, v2);
    }
}

// ===========================================================================
// gemm2 v3: fp16 m16n8k16 GEMM, 128x128 block, 128 threads / 4 warps (2m x 2n),
// 64x64 warp tile (m_t=4, n_t=8) -> 128 smem-bytes per mma (was 192).
// 3-stage cp.async pipeline (16 KB/stage), one sync/chunk, 2 CTAs/SM.
// ===========================================================================
__global__ __launch_bounds__(128, 2)
void gemm2(const uint32_t* __restrict__ Af, const uint32_t* __restrict__ Bf,
           const float* __restrict__ bias, float* __restrict__ C, int N)
{
    extern __shared__ uint32_t sm2[];
    const uint32_t sbase = smem_u32(sm2);
    const int tid  = threadIdx.x;
    const int lane = tid & 31, wid = tid >> 5;
    const int wm   = wid >> 1, wn = wid & 1;
    const int bm   = blockIdx.y * 128, bn = blockIdx.x * 128;

    const uint4* Ab = (const uint4*)(Af + (size_t)blockIdx.y * NCHUNK * 2048);
    const uint4* Bb = (const uint4*)(Bf + (size_t)blockIdx.x * NCHUNK * 2048);

    float acc[4][8][4];
    #pragma unroll
    for (int mi = 0; mi < 4; mi++)
        #pragma unroll
        for (int ni = 0; ni < 8; ni++)
            #pragma unroll
            for (int r = 0; r < 4; r++) acc[mi][ni][r] = 0.f;

    #define COPYC(c, s)                                                       \
        do {                                                                  \
            const uint32_t dA = sbase + (uint32_t)(s) * 16384u;               \
            const uint32_t dB = dA + 8192u;                                   \
            const uint4* sa  = Ab + (c) * 512;                                \
            const uint4* sbp = Bb + (c) * 512;                                \
            _Pragma("unroll")                                                 \
            for (int i = 0; i < 4; i++) {                                     \
                int idx = tid + i * 128;                                      \
                cp_async16(dA + (uint32_t)idx * 16u, sa + idx);               \
                cp_async16(dB + (uint32_t)idx * 16u, sbp + idx);              \
            }                                                                 \
            asm volatile("cp.async.commit_group;" ::: "memory");              \
        } while (0)

    COPYC(0, 0);
    COPYC(1, 1);

    for (int c = 0; c < NCHUNK; c++) {
        if (c + 1 < NCHUNK) {
            asm volatile("cp.async.wait_group 1;" ::: "memory");
        } else {
            asm volatile("cp.async.wait_group 0;" ::: "memory");
        }
        __syncthreads();

        if (c + 2 < NCHUNK) COPYC(c + 2, (c + 2) % 3);

        const uint32_t sA = sbase + (uint32_t)(c % 3) * 16384u;
        const uint32_t sB = sA + 8192u;
        #pragma unroll
        for (int ks = 0; ks < 2; ks++) {
            uint32_t af[4][4], bf[8][2];
            #pragma unroll
            for (int mi = 0; mi < 4; mi++) {
                uint32_t off = (uint32_t)(((ks * 8 + wm * 4 + mi) << 9)
                             + (lane << 4));
                asm volatile("ld.shared.v4.b32 {%0,%1,%2,%3}, [%4];"
                             : "=r"(af[mi][0]), "=r"(af[mi][1]),
                               "=r"(af[mi][2]), "=r"(af[mi][3])
                             : "r"(sA + off));
            }
            #pragma unroll
            for (int ni = 0; ni < 8; ni++) {
                uint32_t off = (uint32_t)(((ks * 16 + wn * 8 + ni) << 8)
                             + (lane << 3));
                asm volatile("ld.shared.v2.b32 {%0,%1}, [%2];"
                             : "=r"(bf[ni][0]), "=r"(bf[ni][1])
                             : "r"(sB + off));
            }
            #pragma unroll
            for (int mi = 0; mi < 4; mi++)
                #pragma unroll
                for (int ni = 0; ni < 8; ni++)
                    mma_f16(acc[mi][ni], af[mi], bf[ni]);
        }
    }

    #pragma unroll
    for (int mi = 0; mi < 4; mi++) {
        int row = bm + wm * 64 + mi * 16 + (lane >> 2);
        #pragma unroll
        for (int ni = 0; ni < 8; ni++) {
            int col = bn + wn * 64 + ni * 8 + (lane & 3) * 2;
            float2 bb = *(const float2*)&bias[col];
            float2 o0, o1;
            o0.x = acc[mi][ni][0] + bb.x;
            o0.y = acc[mi][ni][1] + bb.y;
            o1.x = acc[mi][ni][2] + bb.x;
            o1.y = acc[mi][ni][3] + bb.y;
            *(float2*)&C[(size_t)row * N + col]       = o0;
            *(float2*)&C[(size_t)(row + 8) * N + col] = o1;
        }
    }
    #undef COPYC
}

// ===========================================================================
// conv_kv: K/V -> fp16 fragment blocks, once per (b,h,kv-tile).
// ===========================================================================
__global__ __launch_bounds__(128)
void conv_kv()
{
    const int tid = threadIdx.x;
    const int bh  = blockIdx.y;
    const int kt  = blockIdx.x;
    const int b   = bh / NHEADS;
    const int h   = bh % NHEADS;

    const float* base = g_qkv + (size_t)b * SEQ * QKVN + h * HD;
    uint32_t* out  = g_kvf + ((size_t)bh * 16 + kt) * 4096;
    uint32_t* outV = out + 2048;

    // ---- K tile ----
    {
        const int krr = tid >> 4, kd0 = (tid & 15) * 4;
        const float* Kg = base + DIM + (size_t)(kt * 64) * QKVN;
        #pragma unroll
        for (int p = 0; p < 8; p++) {
            int r = p * 8 + krr;
            float4 v = *(const float4*)(Kg + (size_t)r * QKVN + kd0);
            int nt = r >> 3, k16s = kd0 >> 4, klo = kd0 & 15;
            uint32_t reg  = (klo >= 8) ? 1u : 0u;
            uint32_t lane = (uint32_t)((r & 7) * 4 + ((klo & 7) >> 1));
            uint32_t* oc = out + (nt * 4 + k16s) * 64;
            oc[lane * 2 + reg]       = pack_h2(v.y, v.x);
            oc[(lane + 1) * 2 + reg] = pack_h2(v.w, v.z);
        }
    }
    // ---- V^T tile ----
    {
        const float* Vg = base + 2 * DIM + (size_t)(kt * 64) * QKVN;
        #pragma unroll
        for (int p = 0; p < 8; p++) {
            int task = tid + p * 128;       // 0..1023
            int d  = task & 63;
            int r0 = (task >> 6) * 4;       // 0..60 step 4
            const float* vp = Vg + (size_t)r0 * QKVN + d;
            float v0 = vp[0], v1 = vp[QKVN], v2 = vp[2 * QKVN], v3 = vp[3 * QKVN];
            int nt = d >> 3, n8 = d & 7;
            int k16s = r0 >> 4, klo = r0 & 15;
            uint32_t reg  = (klo >= 8) ? 1u : 0u;
            uint32_t lane = (uint32_t)(n8 * 4 + ((klo & 7) >> 1));
            uint32_t* oc = outV + (nt * 4 + k16s) * 64;
            oc[lane * 2 + reg]       = pack_h2(v1, v0);
            oc[(lane + 1) * 2 + reg] = pack_h2(v3, v2);
        }
    }
}

// ===========================================================================
// fp16 tensor-core flash attention (round-11 winner, unchanged).
// ===========================================================================
__global__ __launch_bounds__(128, 4)
void attn_mma()
{
    extern __shared__ uint32_t smu[];
    const uint32_t sb  = smem_u32(smu);
    const uint32_t VsB = sb + 16384u;
    const uint32_t PsB = sb + 24576u;

    const int tid  = threadIdx.x;
    const int lane = tid & 31, w = tid >> 5;
    const int bh   = blockIdx.y;
    const int b    = bh / NHEADS;
    const int h    = bh % NHEADS;
    const int q0   = blockIdx.x * 64;

    const float* base = g_qkv + (size_t)b * SEQ * QKVN + h * HD;

    const int r0w = w * 16 + (lane >> 2);
    const int c0  = lane & 3;
    const int cc0 = 2 * c0;

    uint32_t qa[4][4];
    {
        const float* Qp0 = base + (size_t)(q0 + r0w) * QKVN;
        const float* Qp1 = Qp0 + 8 * QKVN;
        #pragma unroll
        for (int ks = 0; ks < 4; ks++) {
            float2 a0 = *(const float2*)(Qp0 + ks * 16 + cc0);
            float2 a1 = *(const float2*)(Qp1 + ks * 16 + cc0);
            float2 a2 = *(const float2*)(Qp0 + ks * 16 + 8 + cc0);
            float2 a3 = *(const float2*)(Qp1 + ks * 16 + 8 + cc0);
            qa[ks][0] = pack_h2(a0.y * SC2, a0.x * SC2);
            qa[ks][1] = pack_h2(a1.y * SC2, a1.x * SC2);
            qa[ks][2] = pack_h2(a2.y * SC2, a2.x * SC2);
            qa[ks][3] = pack_h2(a3.y * SC2, a3.x * SC2);
        }
    }

    float oacc[8][4];
    #pragma unroll
    for (int nt = 0; nt < 8; nt++)
        #pragma unroll
        for (int r = 0; r < 4; r++) oacc[nt][r] = 0.f;
    float m0 = -INFINITY, m1 = -INFINITY, l0 = 0.f, l1 = 0.f;

    const uint32_t Pwarp = PsB + (uint32_t)w * 2048u;

    const uint4* kvsrc = (const uint4*)(g_kvf + (size_t)bh * 16 * 4096);

    {
        #pragma unroll
        for (int i = 0; i < 4; i++) {
            int idx = i * 128 + tid;
            cp_async16(sb + (uint32_t)idx * 16u, kvsrc + idx);
        }
        asm volatile("cp.async.commit_group;" ::: "memory");
    }

    for (int kt = 0; kt < SEQ / 64; kt++) {
        asm volatile("cp.async.wait_group 0;" ::: "memory");
        __syncthreads();

        {
            const uint4* src = kvsrc + (size_t)kt * 1024 + 512;
            #pragma unroll
            for (int i = 0; i < 4; i++) {
                int idx = i * 128 + tid;
                cp_async16(VsB + (uint32_t)idx * 16u, src + idx);
            }
            asm volatile("cp.async.commit_group;" ::: "memory");
        }
        if (kt + 1 < SEQ / 64) {
            const uint4* src = kvsrc + (size_t)(kt + 1) * 1024;
            const uint32_t dst = sb + (uint32_t)((kt + 1) & 1) * 8192u;
            #pragma unroll
            for (int i = 0; i < 4; i++) {
                int idx = i * 128 + tid;
                cp_async16(dst + (uint32_t)idx * 16u, src + idx);
            }
            asm volatile("cp.async.commit_group;" ::: "memory");
        }

        const uint32_t KsB = sb + (uint32_t)(kt & 1) * 8192u;

        float sacc[8][4];
        #pragma unroll
        for (int nt = 0; nt < 8; nt++)
            #pragma unroll
            for (int r = 0; r < 4; r++) sacc[nt][r] = 0.f;

        #pragma unroll
        for (int ks = 0; ks < 4; ks++) {
            uint32_t bf[8][2];
            #pragma unroll
            for (int nt = 0; nt < 8; nt++) {
                uint32_t off = (uint32_t)((nt * 4 + ks) << 8) + (lane << 3);
                asm volatile("ld.shared.v2.b32 {%0,%1}, [%2];"
                             : "=r"(bf[nt][0]), "=r"(bf[nt][1])
                             : "r"(KsB + off));
            }
            #pragma unroll
            for (int nt = 0; nt < 8; nt++)
                mma_f16(sacc[nt], qa[ks], bf[nt]);
        }

        if (kt + 1 < SEQ / 64) {
            asm volatile("cp.async.wait_group 1;" ::: "memory");
        } else {
            asm volatile("cp.async.wait_group 0;" ::: "memory");
        }
        __syncthreads();

        float mx0 = -INFINITY, mx1 = -INFINITY;
        #pragma unroll
        for (int nt = 0; nt < 8; nt++) {
            mx0 = fmaxf(mx0, fmaxf(sacc[nt][0], sacc[nt][1]));
            mx1 = fmaxf(mx1, fmaxf(sacc[nt][2], sacc[nt][3]));
        }
        mx0 = fmaxf(mx0, __shfl_xor_sync(0xffffffffu, mx0, 1));
        mx0 = fmaxf(mx0, __shfl_xor_sync(0xffffffffu, mx0, 2));
        mx1 = fmaxf(mx1, __shfl_xor_sync(0xffffffffu, mx1, 1));
        mx1 = fmaxf(mx1, __shfl_xor_sync(0xffffffffu, mx1, 2));
        float mn0 = fmaxf(m0, mx0), mn1 = fmaxf(m1, mx1);
        float a0 = ex2(m0 - mn0), a1 = ex2(m1 - mn1);
        m0 = mn0; m1 = mn1;
        l0 *= a0;  l1 *= a1;

        float sum0 = 0.f, sum1 = 0.f;
        #pragma unroll
        for (int nt = 0; nt < 8; nt++) {
            float p00 = ex2(sacc[nt][0] - m0);
            float p01 = ex2(sacc[nt][1] - m0);
            float p10 = ex2(sacc[nt][2] - m1);
            float p11 = ex2(sacc[nt][3] - m1);
            sum0 += p00 + p01;
            sum1 += p10 + p11;
            oacc[nt][0] *= a0; oacc[nt][1] *= a0;
            oacc[nt][2] *= a1; oacc[nt][3] *= a1;
            uint32_t baddr = Pwarp + (uint32_t)((nt >> 1) * 512)
                           + (uint32_t)(lane << 4) + (uint32_t)((nt & 1) * 8);
            asm volatile("st.shared.b32 [%0], %1;"
                         :: "r"(baddr),     "r"(pack_h2(p01, p00)) : "memory");
            asm volatile("st.shared.b32 [%0], %1;"
                         :: "r"(baddr + 4), "r"(pack_h2(p11, p10)) : "memory");
        }
        sum0 += __shfl_xor_sync(0xffffffffu, sum0, 1);
        sum0 += __shfl_xor_sync(0xffffffffu, sum0, 2);
        sum1 += __shfl_xor_sync(0xffffffffu, sum1, 1);
        sum1 += __shfl_xor_sync(0xffffffffu, sum1, 2);
        l0 += sum0; l1 += sum1;

        #pragma unroll
        for (int ks = 0; ks < 4; ks++) {
            uint32_t pa[4];
            asm volatile("ld.shared.v4.b32 {%0,%1,%2,%3}, [%4];"
                         : "=r"(pa[0]), "=r"(pa[1]), "=r"(pa[2]), "=r"(pa[3])
                         : "r"(Pwarp + (uint32_t)(ks * 512) + (uint32_t)(lane << 4)));
            #pragma unroll
            for (int nt = 0; nt < 8; nt++) {
                uint32_t vb[2];
                uint32_t off = (uint32_t)((nt * 4 + ks) << 8) + (lane << 3);
                asm volatile("ld.shared.v2.b32 {%0,%1}, [%2];"
                             : "=r"(vb[0]), "=r"(vb[1]) : "r"(VsB + off));
                mma_f16(oacc[nt], pa, vb);
            }
        }
    }

    {
        float inv0 = 1.f / l0, inv1 = 1.f / l1;
        float* O0 = g_att + (size_t)(b * SEQ + q0 + r0w) * DIM + h * HD;
        float* O1 = O0 + 8 * DIM;
        #pragma unroll
        for (int nt = 0; nt < 8; nt++) {
            int col = nt * 8 + cc0;
            float2 v0 = {oacc[nt][0] * inv0, oacc[nt][1] * inv0};
            float2 v1 = {oacc[nt][2] * inv1, oacc[nt][3] * inv1};
            *(float2*)(O0 + col) = v0;
            *(float2*)(O1 + col) = v1;
        }
    }
}

// ---------------------------------------------------------------------------
extern "C" void kernel_launch(void* const* d_in, const int* in_sizes, int n_in,
                              void* d_out, int out_size)
{
    const float* x      = (const float*)d_in[0];
    const float* w_qkv  = (const float*)d_in[1];
    const float* b_qkv  = (const float*)d_in[2];
    const float* w_proj = (const float*)d_in[3];
    const float* b_proj = (const float*)d_in[4];
    float* out = (float*)d_out;

    float *qkv = nullptr, *att = nullptr;
    uint32_t *xf = nullptr, *af2 = nullptr, *wqf = nullptr, *wpf = nullptr;
    cudaGetSymbolAddress((void**)&qkv, g_qkv);
    cudaGetSymbolAddress((void**)&att, g_att);
    cudaGetSymbolAddress((void**)&xf,  g_xf);
    cudaGetSymbolAddress((void**)&af2, g_af2);
    cudaGetSymbolAddress((void**)&wqf, g_wqf);
    cudaGetSymbolAddress((void**)&wpf, g_wpf);

    const int gemm_smem = 49152;   // 3 stages x 16 KB
    const int attn_smem = 32768;   // K0|K1|V|Ps = 4 x 8 KB
    cudaFuncSetAttribute(gemm2,
                         cudaFuncAttributeMaxDynamicSharedMemorySize, gemm_smem);
    cudaFuncSetAttribute(attn_mma,
                         cudaFuncAttributeMaxDynamicSharedMemorySize, attn_smem);

    // 0) operand conversions (x, weights) -> fp16 fragments
    conv_a<<<dim3(64, 8), 256>>>(x, xf);
    conv_b<<<dim3(18, 8), 256>>>(w_qkv, wqf, QKVN);
    conv_b<<<dim3(6, 8),  256>>>(w_proj, wpf, DIM);

    // 1) QKV projection (fp16 tensor cores, 64x64 warp tiles)
    gemm2<<<dim3(QKVN / 128, MROWS / 128), 128, gemm_smem>>>(
        xf, wqf, b_qkv, qkv, QKVN);

    // 2) attention
    conv_kv<<<dim3(16, BATCH * NHEADS), 128>>>();
    attn_mma<<<dim3(SEQ / 64, BATCH * NHEADS), 128, attn_smem>>>();

    // 3) output projection
    conv_a<<<dim3(64, 8), 256>>>(att, af2);
    gemm2<<<dim3(DIM / 128, MROWS / 128), 128, gemm_smem>>>(
        af2, wpf, b_proj, out, DIM);
}